// round 1
// baseline (speedup 1.0000x reference)
#include <cuda_runtime.h>
#include <math.h>

#define BATCH  4
#define SEQ    2048
#define NHEADS 16
#define DK     64
#define DMODEL 1024
#define ROWS   (BATCH * SEQ)   // 8192

// Scratch (static device globals — no runtime allocation allowed)
__device__ float g_Q[ROWS * DMODEL];        // 32 MB
__device__ float g_KV[ROWS * 2 * DMODEL];   // 64 MB
__device__ float g_attn[ROWS * DMODEL];     // 32 MB

// ---------------------------------------------------------------------------
// Classic 128x128x8 fp32 SGEMM: C[M,N] = A[M,K] @ B[K,N], all row-major.
// Requires M%128==0, N%128==0, K%8==0 (true for all three uses).
// 256 threads, each computes an 8x8 register tile.
// ---------------------------------------------------------------------------
__global__ __launch_bounds__(256) void sgemm128(const float* __restrict__ A,
                                                const float* __restrict__ B,
                                                float* __restrict__ C,
                                                int M, int N, int K) {
    __shared__ float As[8][128];   // transposed A tile: As[k][m]
    __shared__ float Bs[8][128];   // Bs[k][n]

    const int tid = threadIdx.x;
    const int bx = blockIdx.x;     // N tile
    const int by = blockIdx.y;     // M tile
    const int tx = tid & 15;       // 16x16 thread grid
    const int ty = tid >> 4;

    float acc[8][8];
#pragma unroll
    for (int i = 0; i < 8; i++)
#pragma unroll
        for (int j = 0; j < 8; j++) acc[i][j] = 0.f;

    const int a_row = tid >> 1;            // 0..127
    const int a_col = (tid & 1) * 4;       // 0 or 4
    const int b_row = tid >> 5;            // 0..7
    const int b_col = (tid & 31) * 4;      // 0..124

    const float* Ab = A + (size_t)(by * 128 + a_row) * K + a_col;
    const float* Bb = B + (size_t)b_row * N + bx * 128 + b_col;

    for (int k0 = 0; k0 < K; k0 += 8) {
        float4 a4 = *(const float4*)(Ab + k0);
        As[a_col + 0][a_row] = a4.x;
        As[a_col + 1][a_row] = a4.y;
        As[a_col + 2][a_row] = a4.z;
        As[a_col + 3][a_row] = a4.w;
        *(float4*)&Bs[b_row][b_col] = *(const float4*)(Bb + (size_t)k0 * N);
        __syncthreads();

#pragma unroll
        for (int kk = 0; kk < 8; kk++) {
            float a_frag[8], b_frag[8];
            *(float4*)&a_frag[0] = *(const float4*)&As[kk][ty * 8];
            *(float4*)&a_frag[4] = *(const float4*)&As[kk][ty * 8 + 4];
            *(float4*)&b_frag[0] = *(const float4*)&Bs[kk][tx * 8];
            *(float4*)&b_frag[4] = *(const float4*)&Bs[kk][tx * 8 + 4];
#pragma unroll
            for (int i = 0; i < 8; i++)
#pragma unroll
                for (int j = 0; j < 8; j++)
                    acc[i][j] += a_frag[i] * b_frag[j];
        }
        __syncthreads();
    }

#pragma unroll
    for (int i = 0; i < 8; i++) {
        float* cp = C + (size_t)(by * 128 + ty * 8 + i) * N + bx * 128 + tx * 8;
        *(float4*)cp       = make_float4(acc[i][0], acc[i][1], acc[i][2], acc[i][3]);
        *(float4*)(cp + 4) = make_float4(acc[i][4], acc[i][5], acc[i][6], acc[i][7]);
    }
}

// ---------------------------------------------------------------------------
// Flash attention, fp32, one head per blockIdx.y, one batch per blockIdx.z.
// 128 query rows per block, one row per thread (q and o accumulator in regs).
// K/V tiles of 64 keys staged in shared; scores staged in padded shared row.
// Q layout: [b, n, h*64 + d] (output of Q projection, row-major [8192,1024]).
// KV layout: [b, n, 2048]; K at col h*64, V at col 1024 + h*64.
// ---------------------------------------------------------------------------
#define SS_PITCH 65

__global__ __launch_bounds__(128) void flash_attn(const float* __restrict__ Q,
                                                  const float* __restrict__ KV,
                                                  float* __restrict__ O) {
    extern __shared__ float smem[];
    float* Ks = smem;              // 64 * 64
    float* Vs = smem + 4096;       // 64 * 64
    float* Ss = smem + 8192;       // 128 * SS_PITCH

    const int b = blockIdx.z;
    const int h = blockIdx.y;
    const int t = threadIdx.x;                 // owns query row qrow
    const int qrow = blockIdx.x * 128 + t;
    const float scale = 0.125f;                // 1/sqrt(64)

    float q[64], o[64];
    const float* qp = Q + (size_t)(b * SEQ + qrow) * DMODEL + h * DK;
#pragma unroll
    for (int d = 0; d < 64; d += 4) {
        float4 v = *(const float4*)(qp + d);
        q[d] = v.x * scale; q[d + 1] = v.y * scale;
        q[d + 2] = v.z * scale; q[d + 3] = v.w * scale;
        o[d] = 0.f; o[d + 1] = 0.f; o[d + 2] = 0.f; o[d + 3] = 0.f;
    }
    float m = -1e30f, l = 0.f;

    for (int j0 = 0; j0 < SEQ; j0 += 64) {
        // Cooperative coalesced load of K and V tiles (1024 float4s each, 8/thread)
#pragma unroll
        for (int i = 0; i < 8; i++) {
            int idx = t + 128 * i;             // float4 index 0..1023
            int r = idx >> 4;
            int c = (idx & 15) * 4;
            const float* kp = KV + (size_t)(b * SEQ + j0 + r) * (2 * DMODEL) + h * DK + c;
            *(float4*)(Ks + r * 64 + c) = *(const float4*)kp;
            *(float4*)(Vs + r * 64 + c) = *(const float4*)(kp + DMODEL);
        }
        __syncthreads();

        // scores for this thread's row (broadcast LDS of K rows)
        float tmax = -1e30f;
        for (int j = 0; j < 64; j++) {
            const float4* kr = (const float4*)(Ks + j * 64);
            float s = 0.f;
#pragma unroll
            for (int d4 = 0; d4 < 16; d4++) {
                float4 k4 = kr[d4];
                s += q[d4 * 4 + 0] * k4.x + q[d4 * 4 + 1] * k4.y
                   + q[d4 * 4 + 2] * k4.z + q[d4 * 4 + 3] * k4.w;
            }
            Ss[t * SS_PITCH + j] = s;
            tmax = fmaxf(tmax, s);
        }

        // online softmax rescale
        float m_new = fmaxf(m, tmax);
        float corr = __expf(m - m_new);
        l *= corr;
#pragma unroll
        for (int d = 0; d < 64; d++) o[d] *= corr;

        // accumulate P @ V (broadcast LDS of V rows)
        for (int j = 0; j < 64; j++) {
            float p = __expf(Ss[t * SS_PITCH + j] - m_new);
            l += p;
            const float4* vr = (const float4*)(Vs + j * 64);
#pragma unroll
            for (int d4 = 0; d4 < 16; d4++) {
                float4 v4 = vr[d4];
                o[d4 * 4 + 0] += p * v4.x; o[d4 * 4 + 1] += p * v4.y;
                o[d4 * 4 + 2] += p * v4.z; o[d4 * 4 + 3] += p * v4.w;
            }
        }
        m = m_new;
        __syncthreads();
    }

    const float inv = 1.f / l;
    float* op = O + (size_t)(b * SEQ + qrow) * DMODEL + h * DK;
#pragma unroll
    for (int d = 0; d < 64; d += 4) {
        float4 v;
        v.x = o[d] * inv; v.y = o[d + 1] * inv;
        v.z = o[d + 2] * inv; v.w = o[d + 3] * inv;
        *(float4*)(op + d) = v;
    }
}

// ---------------------------------------------------------------------------
extern "C" void kernel_launch(void* const* d_in, const int* in_sizes, int n_in,
                              void* d_out, int out_size) {
    const float* x   = (const float*)d_in[0];   // [4, 2048, 1024]
    const float* Wq  = (const float*)d_in[1];   // [1024, 1024]
    const float* Wkv = (const float*)d_in[2];   // [1024, 2048]
    const float* Wo  = (const float*)d_in[3];   // [1024, 1024]
    float* out = (float*)d_out;                 // [4, 2048, 1024]

    float *pQ, *pKV, *pA;
    cudaGetSymbolAddress((void**)&pQ,  g_Q);
    cudaGetSymbolAddress((void**)&pKV, g_KV);
    cudaGetSymbolAddress((void**)&pA,  g_attn);

    // Q = x @ Wq   [8192,1024] x [1024,1024]
    sgemm128<<<dim3(DMODEL / 128, ROWS / 128), 256>>>(x, Wq, pQ, ROWS, DMODEL, DMODEL);
    // KV = x @ Wkv [8192,1024] x [1024,2048]
    sgemm128<<<dim3(2 * DMODEL / 128, ROWS / 128), 256>>>(x, Wkv, pKV, ROWS, 2 * DMODEL, DMODEL);

    // flash attention
    int smem_bytes = (4096 + 4096 + 128 * SS_PITCH) * (int)sizeof(float);  // 66048
    cudaFuncSetAttribute(flash_attn, cudaFuncAttributeMaxDynamicSharedMemorySize, smem_bytes);
    flash_attn<<<dim3(SEQ / 128, NHEADS, BATCH), 128, smem_bytes>>>(pQ, pKV, pA);

    // out = attn @ Wo [8192,1024] x [1024,1024]
    sgemm128<<<dim3(DMODEL / 128, ROWS / 128), 256>>>(pA, Wo, out, ROWS, DMODEL, DMODEL);
}

// round 3
// speedup vs baseline: 2.1471x; 2.1471x over previous
#include <cuda_runtime.h>
#include <cuda_bf16.h>
#include <cstdint>
#include <math.h>

#define BATCH  4
#define SEQ    2048
#define NHEADS 16
#define DK     64
#define DMODEL 1024
#define ROWS   (BATCH * SEQ)   // 8192
#define GK     1024            // K dim of all projection GEMMs

// ---------------------------------------------------------------------------
// Scratch (static device globals — no runtime allocation allowed)
// ---------------------------------------------------------------------------
__device__ float g_Q[ROWS * DMODEL];          // 32 MB
__device__ float g_KV[ROWS * 2 * DMODEL];     // 64 MB
__device__ float g_attn[ROWS * DMODEL];       // 32 MB

__device__ __nv_bfloat16 g_xh[ROWS * GK];     // 16 MB
__device__ __nv_bfloat16 g_xl[ROWS * GK];
__device__ __nv_bfloat16 g_ah[ROWS * GK];
__device__ __nv_bfloat16 g_al[ROWS * GK];
// transposed weights [N, K] bf16 hi/lo
__device__ __nv_bfloat16 g_wq_h[DMODEL * GK];
__device__ __nv_bfloat16 g_wq_l[DMODEL * GK];
__device__ __nv_bfloat16 g_wkv_h[2 * DMODEL * GK];
__device__ __nv_bfloat16 g_wkv_l[2 * DMODEL * GK];
__device__ __nv_bfloat16 g_wo_h[DMODEL * GK];
__device__ __nv_bfloat16 g_wo_l[DMODEL * GK];

// ---------------------------------------------------------------------------
// helpers
// ---------------------------------------------------------------------------
__device__ __forceinline__ uint32_t smem_u32(const void* p) {
    uint32_t a;
    asm("{ .reg .u64 t; cvta.to.shared.u64 t, %1; cvt.u32.u64 %0, t; }"
        : "=r"(a) : "l"(p));
    return a;
}

#define CP_ASYNC16(dst, src) \
    asm volatile("cp.async.cg.shared.global [%0], [%1], 16;" \
                 :: "r"(dst), "l"(src) : "memory")
#define CP_COMMIT() asm volatile("cp.async.commit_group;" ::: "memory")
#define CP_WAIT0()  asm volatile("cp.async.wait_group 0;" ::: "memory")

__device__ __forceinline__ void ldmatrix_x4(uint32_t* r, uint32_t addr) {
    asm volatile("ldmatrix.sync.aligned.m8n8.x4.shared.b16 {%0,%1,%2,%3}, [%4];"
                 : "=r"(r[0]), "=r"(r[1]), "=r"(r[2]), "=r"(r[3]) : "r"(addr));
}
__device__ __forceinline__ void ldmatrix_x2(uint32_t* r, uint32_t addr) {
    asm volatile("ldmatrix.sync.aligned.m8n8.x2.shared.b16 {%0,%1}, [%2];"
                 : "=r"(r[0]), "=r"(r[1]) : "r"(addr));
}
__device__ __forceinline__ void mma_16816(float* c, const uint32_t* a,
                                          const uint32_t* b) {
    asm volatile(
        "mma.sync.aligned.m16n8k16.row.col.f32.bf16.bf16.f32 "
        "{%0,%1,%2,%3}, {%4,%5,%6,%7}, {%8,%9}, {%0,%1,%2,%3};"
        : "+f"(c[0]), "+f"(c[1]), "+f"(c[2]), "+f"(c[3])
        : "r"(a[0]), "r"(a[1]), "r"(a[2]), "r"(a[3]), "r"(b[0]), "r"(b[1]));
}

// ---------------------------------------------------------------------------
// split-bf16 HMMA GEMM: C[M,N]fp32 = A[M,GK] @ W[GK,N]
//   A as Ah/Al bf16 [M,GK] row-major; W transposed as Bh/Bl bf16 [N,GK].
//   C = Ah·Bh^T + Ah·Bl^T + Al·Bh^T
// CTA 128x128, K staged 32, 8 warps (2 M x 4 N), warp tile 64x32.
// Smem tiles: 128 rows x 32 bf16, pitch 40 bf16 (80B) -> ldmatrix conflict-free.
// ---------------------------------------------------------------------------
#define TPITCH   40                     // bf16 units
#define TPITCH_B 80                     // bytes
#define TILE_B   (128 * TPITCH_B)       // 10240 bytes per tile
#define STAGE_B  (4 * TILE_B)           // Ah, Al, Bh, Bl
#define SM_GEMM_TOTAL (2 * STAGE_B)     // 81920

__global__ __launch_bounds__(256, 1)
void gemm_mma(const __nv_bfloat16* __restrict__ Ah,
              const __nv_bfloat16* __restrict__ Al,
              const __nv_bfloat16* __restrict__ Bh,
              const __nv_bfloat16* __restrict__ Bl,
              float* __restrict__ C, int N) {
    extern __shared__ char smem[];
    const uint32_t sb = smem_u32(smem);
    const int tid  = threadIdx.x;
    const int wid  = tid >> 5;
    const int lane = tid & 31;
    const int warp_m = wid >> 2;        // 0..1  -> m offset *64
    const int warp_n = wid & 3;         // 0..3  -> n offset *32
    const int bx = blockIdx.x;          // N tile
    const int by = blockIdx.y;          // M tile

    const __nv_bfloat16* pAh = Ah + (size_t)(by * 128) * GK;
    const __nv_bfloat16* pAl = Al + (size_t)(by * 128) * GK;
    const __nv_bfloat16* pBh = Bh + (size_t)(bx * 128) * GK;
    const __nv_bfloat16* pBl = Bl + (size_t)(bx * 128) * GK;

    float acc[4][4][4];
#pragma unroll
    for (int i = 0; i < 4; i++)
#pragma unroll
        for (int j = 0; j < 4; j++)
#pragma unroll
            for (int v = 0; v < 4; v++) acc[i][j][v] = 0.f;

    // cooperative load indices: 512 float4 per tile, 2 per thread
    const int r0 = (tid * 2) >> 2;           // row of first float4
    const int c0 = (tid * 2) & 3;            // col-chunk (8 bf16) of first
    const int r1 = (tid * 2 + 1) >> 2;
    const int c1 = (tid * 2 + 1) & 3;

    auto issue_stage = [&](int buf, int k0) {
        const uint32_t s0 = sb + buf * STAGE_B;
        const size_t g0 = (size_t)r0 * GK + k0 + c0 * 8;
        const size_t g1 = (size_t)r1 * GK + k0 + c1 * 8;
        const uint32_t o0 = r0 * TPITCH_B + c0 * 16;
        const uint32_t o1 = r1 * TPITCH_B + c1 * 16;
        CP_ASYNC16(s0 + o0,              pAh + g0);
        CP_ASYNC16(s0 + o1,              pAh + g1);
        CP_ASYNC16(s0 + TILE_B + o0,     pAl + g0);
        CP_ASYNC16(s0 + TILE_B + o1,     pAl + g1);
        CP_ASYNC16(s0 + 2 * TILE_B + o0, pBh + g0);
        CP_ASYNC16(s0 + 2 * TILE_B + o1, pBh + g1);
        CP_ASYNC16(s0 + 3 * TILE_B + o0, pBl + g0);
        CP_ASYNC16(s0 + 3 * TILE_B + o1, pBl + g1);
        CP_COMMIT();
    };

    // ldmatrix lane addressing (byte offsets within a tile)
    const uint32_t a_row = warp_m * 64 + (lane & 15);
    const uint32_t a_kof = (lane >> 4) * 8;
    const uint32_t b_row = warp_n * 32 + (lane & 7);
    const uint32_t b_kof = ((lane >> 3) & 1) * 8;

    issue_stage(0, 0);

    for (int ks = 0; ks < GK / 32; ks++) {
        const int buf = ks & 1;
        CP_WAIT0();
        __syncthreads();
        if (ks + 1 < GK / 32) issue_stage(buf ^ 1, (ks + 1) * 32);

        const uint32_t s0 = sb + buf * STAGE_B;
        // pass 0: Ah*Bh, pass 1: Ah*Bl, pass 2: Al*Bh
#pragma unroll
        for (int pass = 0; pass < 3; pass++) {
            const uint32_t aoff = (pass == 2) ? TILE_B : 0;
            const uint32_t boff = (pass == 1) ? 3u * TILE_B : 2u * TILE_B;
#pragma unroll
            for (int kk = 0; kk < 32; kk += 16) {
                uint32_t afr[4][4], bfr[4][2];
#pragma unroll
                for (int mt = 0; mt < 4; mt++)
                    ldmatrix_x4(afr[mt],
                        s0 + aoff + (a_row + mt * 16) * TPITCH_B
                           + (kk + a_kof) * 2);
#pragma unroll
                for (int nt = 0; nt < 4; nt++)
                    ldmatrix_x2(bfr[nt],
                        s0 + boff + (b_row + nt * 8) * TPITCH_B
                           + (kk + b_kof) * 2);
#pragma unroll
                for (int mt = 0; mt < 4; mt++)
#pragma unroll
                    for (int nt = 0; nt < 4; nt++)
                        mma_16816(acc[mt][nt], afr[mt], bfr[nt]);
            }
        }
        __syncthreads();
    }

    // epilogue: fp32 store
    const int crow = by * 128 + warp_m * 64 + (lane >> 2);
    const int ccol = bx * 128 + warp_n * 32 + (lane & 3) * 2;
#pragma unroll
    for (int mt = 0; mt < 4; mt++) {
#pragma unroll
        for (int nt = 0; nt < 4; nt++) {
            float* p0 = C + (size_t)(crow + mt * 16) * N + ccol + nt * 8;
            float* p1 = p0 + 8 * (size_t)N;
            *(float2*)p0 = make_float2(acc[mt][nt][0], acc[mt][nt][1]);
            *(float2*)p1 = make_float2(acc[mt][nt][2], acc[mt][nt][3]);
        }
    }
}

// ---------------------------------------------------------------------------
// fp32 -> (hi, lo) bf16 split, elementwise (n must be /4)
// ---------------------------------------------------------------------------
__global__ void split_kernel(const float* __restrict__ s,
                             __nv_bfloat16* __restrict__ h,
                             __nv_bfloat16* __restrict__ l, int n4) {
    int i = blockIdx.x * blockDim.x + threadIdx.x;
    if (i >= n4) return;
    float4 v = ((const float4*)s)[i];
    __nv_bfloat16 h0 = __float2bfloat16(v.x);
    __nv_bfloat16 h1 = __float2bfloat16(v.y);
    __nv_bfloat16 h2 = __float2bfloat16(v.z);
    __nv_bfloat16 h3 = __float2bfloat16(v.w);
    __nv_bfloat162* hp = (__nv_bfloat162*)h;
    __nv_bfloat162* lp = (__nv_bfloat162*)l;
    hp[2 * i]     = __nv_bfloat162(h0, h1);
    hp[2 * i + 1] = __nv_bfloat162(h2, h3);
    lp[2 * i]     = __nv_bfloat162(__float2bfloat16(v.x - __bfloat162float(h0)),
                                   __float2bfloat16(v.y - __bfloat162float(h1)));
    lp[2 * i + 1] = __nv_bfloat162(__float2bfloat16(v.z - __bfloat162float(h2)),
                                   __float2bfloat16(v.w - __bfloat162float(h3)));
}

// ---------------------------------------------------------------------------
// Transposed split: W fp32 [K, N] -> Wt hi/lo bf16 [N, K]
// ---------------------------------------------------------------------------
__global__ void splitT_kernel(const float* __restrict__ W,
                              __nv_bfloat16* __restrict__ th,
                              __nv_bfloat16* __restrict__ tl, int K, int N) {
    __shared__ float t[32][33];
    const int x0 = blockIdx.x * 32;   // N base
    const int y0 = blockIdx.y * 32;   // K base
    const int tx = threadIdx.x;
#pragma unroll
    for (int j = threadIdx.y; j < 32; j += 8)
        t[j][tx] = W[(size_t)(y0 + j) * N + x0 + tx];
    __syncthreads();
#pragma unroll
    for (int j = threadIdx.y; j < 32; j += 8) {
        float v = t[tx][j];   // = W[y0+tx][x0+j]
        size_t o = (size_t)(x0 + j) * K + y0 + tx;
        __nv_bfloat16 hv = __float2bfloat16(v);
        th[o] = hv;
        tl[o] = __float2bfloat16(v - __bfloat162float(hv));
    }
}

// ---------------------------------------------------------------------------
// Flash attention, fp32 (unchanged from R1)
// ---------------------------------------------------------------------------
#define SS_PITCH 65

__global__ __launch_bounds__(128) void flash_attn(const float* __restrict__ Q,
                                                  const float* __restrict__ KV,
                                                  float* __restrict__ O) {
    extern __shared__ float smemf[];
    float* Ks = smemf;
    float* Vs = smemf + 4096;
    float* Ss = smemf + 8192;

    const int b = blockIdx.z;
    const int h = blockIdx.y;
    const int t = threadIdx.x;
    const int qrow = blockIdx.x * 128 + t;
    const float scale = 0.125f;

    float q[64], o[64];
    const float* qp = Q + (size_t)(b * SEQ + qrow) * DMODEL + h * DK;
#pragma unroll
    for (int d = 0; d < 64; d += 4) {
        float4 v = *(const float4*)(qp + d);
        q[d] = v.x * scale; q[d + 1] = v.y * scale;
        q[d + 2] = v.z * scale; q[d + 3] = v.w * scale;
        o[d] = 0.f; o[d + 1] = 0.f; o[d + 2] = 0.f; o[d + 3] = 0.f;
    }
    float m = -1e30f, l = 0.f;

    for (int j0 = 0; j0 < SEQ; j0 += 64) {
#pragma unroll
        for (int i = 0; i < 8; i++) {
            int idx = t + 128 * i;
            int r = idx >> 4;
            int c = (idx & 15) * 4;
            const float* kp = KV + (size_t)(b * SEQ + j0 + r) * (2 * DMODEL) + h * DK + c;
            *(float4*)(Ks + r * 64 + c) = *(const float4*)kp;
            *(float4*)(Vs + r * 64 + c) = *(const float4*)(kp + DMODEL);
        }
        __syncthreads();

        float tmax = -1e30f;
        for (int j = 0; j < 64; j++) {
            const float4* kr = (const float4*)(Ks + j * 64);
            float s = 0.f;
#pragma unroll
            for (int d4 = 0; d4 < 16; d4++) {
                float4 k4 = kr[d4];
                s += q[d4 * 4 + 0] * k4.x + q[d4 * 4 + 1] * k4.y
                   + q[d4 * 4 + 2] * k4.z + q[d4 * 4 + 3] * k4.w;
            }
            Ss[t * SS_PITCH + j] = s;
            tmax = fmaxf(tmax, s);
        }

        float m_new = fmaxf(m, tmax);
        float corr = __expf(m - m_new);
        l *= corr;
#pragma unroll
        for (int d = 0; d < 64; d++) o[d] *= corr;

        for (int j = 0; j < 64; j++) {
            float p = __expf(Ss[t * SS_PITCH + j] - m_new);
            l += p;
            const float4* vr = (const float4*)(Vs + j * 64);
#pragma unroll
            for (int d4 = 0; d4 < 16; d4++) {
                float4 v4 = vr[d4];
                o[d4 * 4 + 0] += p * v4.x; o[d4 * 4 + 1] += p * v4.y;
                o[d4 * 4 + 2] += p * v4.z; o[d4 * 4 + 3] += p * v4.w;
            }
        }
        m = m_new;
        __syncthreads();
    }

    const float inv = 1.f / l;
    float* op = O + (size_t)(b * SEQ + qrow) * DMODEL + h * DK;
#pragma unroll
    for (int d = 0; d < 64; d += 4) {
        float4 v;
        v.x = o[d] * inv; v.y = o[d + 1] * inv;
        v.z = o[d + 2] * inv; v.w = o[d + 3] * inv;
        *(float4*)(op + d) = v;
    }
}

// ---------------------------------------------------------------------------
extern "C" void kernel_launch(void* const* d_in, const int* in_sizes, int n_in,
                              void* d_out, int out_size) {
    const float* x   = (const float*)d_in[0];   // [4, 2048, 1024]
    const float* Wq  = (const float*)d_in[1];   // [1024, 1024]
    const float* Wkv = (const float*)d_in[2];   // [1024, 2048]
    const float* Wo  = (const float*)d_in[3];   // [1024, 1024]
    float* out = (float*)d_out;

    float *pQ, *pKV, *pA;
    cudaGetSymbolAddress((void**)&pQ,  g_Q);
    cudaGetSymbolAddress((void**)&pKV, g_KV);
    cudaGetSymbolAddress((void**)&pA,  g_attn);
    __nv_bfloat16 *xh, *xl, *ah, *al, *wqh, *wql, *wkvh, *wkvl, *woh, *wol;
    cudaGetSymbolAddress((void**)&xh,   g_xh);
    cudaGetSymbolAddress((void**)&xl,   g_xl);
    cudaGetSymbolAddress((void**)&ah,   g_ah);
    cudaGetSymbolAddress((void**)&al,   g_al);
    cudaGetSymbolAddress((void**)&wqh,  g_wq_h);
    cudaGetSymbolAddress((void**)&wql,  g_wq_l);
    cudaGetSymbolAddress((void**)&wkvh, g_wkv_h);
    cudaGetSymbolAddress((void**)&wkvl, g_wkv_l);
    cudaGetSymbolAddress((void**)&woh,  g_wo_h);
    cudaGetSymbolAddress((void**)&wol,  g_wo_l);

    cudaFuncSetAttribute(gemm_mma, cudaFuncAttributeMaxDynamicSharedMemorySize,
                         SM_GEMM_TOTAL);
    int flash_smem = (4096 + 4096 + 128 * SS_PITCH) * (int)sizeof(float);
    cudaFuncSetAttribute(flash_attn, cudaFuncAttributeMaxDynamicSharedMemorySize,
                         flash_smem);

    // 1) split inputs / weights
    {
        int n4 = ROWS * GK / 4;
        split_kernel<<<(n4 + 255) / 256, 256>>>(x, xh, xl, n4);
    }
    splitT_kernel<<<dim3(DMODEL / 32, GK / 32), dim3(32, 8)>>>(Wq, wqh, wql, GK, DMODEL);
    splitT_kernel<<<dim3(2 * DMODEL / 32, GK / 32), dim3(32, 8)>>>(Wkv, wkvh, wkvl, GK, 2 * DMODEL);
    splitT_kernel<<<dim3(DMODEL / 32, GK / 32), dim3(32, 8)>>>(Wo, woh, wol, GK, DMODEL);

    // 2) Q and KV projections on tensor cores (HMMA)
    gemm_mma<<<dim3(DMODEL / 128, ROWS / 128), 256, SM_GEMM_TOTAL>>>(
        xh, xl, wqh, wql, pQ, DMODEL);
    gemm_mma<<<dim3(2 * DMODEL / 128, ROWS / 128), 256, SM_GEMM_TOTAL>>>(
        xh, xl, wkvh, wkvl, pKV, 2 * DMODEL);

    // 3) attention (fp32 flash)
    flash_attn<<<dim3(SEQ / 128, NHEADS, BATCH), 128, flash_smem>>>(pQ, pKV, pA);

    // 4) output projection
    {
        int n4 = ROWS * GK / 4;
        split_kernel<<<(n4 + 255) / 256, 256>>>(pA, ah, al, n4);
    }
    gemm_mma<<<dim3(DMODEL / 128, ROWS / 128), 256, SM_GEMM_TOTAL>>>(
        ah, al, woh, wol, out, DMODEL);
}

// round 4
// speedup vs baseline: 4.9818x; 2.3203x over previous
#include <cuda_runtime.h>
#include <cuda_bf16.h>
#include <cstdint>
#include <math.h>

#define BATCH  4
#define SEQ    2048
#define NHEADS 16
#define DK     64
#define DMODEL 1024
#define ROWS   (BATCH * SEQ)   // 8192
#define GK     1024

// ---------------------------------------------------------------------------
// Scratch (static device globals)
// ---------------------------------------------------------------------------
__device__ __nv_bfloat16 g_xh[ROWS * GK];
__device__ __nv_bfloat16 g_xl[ROWS * GK];
__device__ __nv_bfloat16 g_qh[ROWS * DMODEL];       // Q proj hi (pre-scaled)
__device__ __nv_bfloat16 g_ql[ROWS * DMODEL];
__device__ __nv_bfloat16 g_kvh[ROWS * 2 * DMODEL];
__device__ __nv_bfloat16 g_kvl[ROWS * 2 * DMODEL];
__device__ __nv_bfloat16 g_oh[ROWS * DMODEL];       // attention out hi
__device__ __nv_bfloat16 g_ol[ROWS * DMODEL];
__device__ __nv_bfloat16 g_wq_h[DMODEL * GK];
__device__ __nv_bfloat16 g_wq_l[DMODEL * GK];
__device__ __nv_bfloat16 g_wkv_h[2 * DMODEL * GK];
__device__ __nv_bfloat16 g_wkv_l[2 * DMODEL * GK];
__device__ __nv_bfloat16 g_wo_h[DMODEL * GK];
__device__ __nv_bfloat16 g_wo_l[DMODEL * GK];

// ---------------------------------------------------------------------------
// helpers
// ---------------------------------------------------------------------------
__device__ __forceinline__ uint32_t smem_u32(const void* p) {
    uint32_t a;
    asm("{ .reg .u64 t; cvta.to.shared.u64 t, %1; cvt.u32.u64 %0, t; }"
        : "=r"(a) : "l"(p));
    return a;
}

#define CP_ASYNC16(dst, src) \
    asm volatile("cp.async.cg.shared.global [%0], [%1], 16;" \
                 :: "r"(dst), "l"(src) : "memory")
#define CP_COMMIT()   asm volatile("cp.async.commit_group;" ::: "memory")
#define CP_WAIT_ALL() asm volatile("cp.async.wait_group 0;" ::: "memory")
#define CP_WAIT_ONE() asm volatile("cp.async.wait_group 1;" ::: "memory")

__device__ __forceinline__ void ldmatrix_x4(uint32_t* r, uint32_t addr) {
    asm volatile("ldmatrix.sync.aligned.m8n8.x4.shared.b16 {%0,%1,%2,%3}, [%4];"
                 : "=r"(r[0]), "=r"(r[1]), "=r"(r[2]), "=r"(r[3]) : "r"(addr));
}
__device__ __forceinline__ void ldmatrix_x2(uint32_t* r, uint32_t addr) {
    asm volatile("ldmatrix.sync.aligned.m8n8.x2.shared.b16 {%0,%1}, [%2];"
                 : "=r"(r[0]), "=r"(r[1]) : "r"(addr));
}
__device__ __forceinline__ void ldmatrix_x2_trans(uint32_t* r, uint32_t addr) {
    asm volatile("ldmatrix.sync.aligned.m8n8.x2.trans.shared.b16 {%0,%1}, [%2];"
                 : "=r"(r[0]), "=r"(r[1]) : "r"(addr));
}
__device__ __forceinline__ void mma_16816(float* c, const uint32_t* a,
                                          const uint32_t* b) {
    asm volatile(
        "mma.sync.aligned.m16n8k16.row.col.f32.bf16.bf16.f32 "
        "{%0,%1,%2,%3}, {%4,%5,%6,%7}, {%8,%9}, {%0,%1,%2,%3};"
        : "+f"(c[0]), "+f"(c[1]), "+f"(c[2]), "+f"(c[3])
        : "r"(a[0]), "r"(a[1]), "r"(a[2]), "r"(a[3]), "r"(b[0]), "r"(b[1]));
}

// pack (p0, p1) into bf16x2 hi word + bf16x2 lo-residual word
__device__ __forceinline__ void split2(float p0, float p1,
                                       uint32_t& h, uint32_t& l) {
    __nv_bfloat162 hb = __floats2bfloat162_rn(p0, p1);
    __nv_bfloat162 lb = __floats2bfloat162_rn(p0 - __bfloat162float(hb.x),
                                              p1 - __bfloat162float(hb.y));
    h = *(uint32_t*)&hb;
    l = *(uint32_t*)&lb;
}

// ---------------------------------------------------------------------------
// split-bf16 HMMA GEMM: C = A @ W^T (A [M,GK] hi/lo, W [N,GK] hi/lo)
// HILO=false -> fp32 C; HILO=true -> Ch/Cl bf16 hi/lo output, scaled.
// CTA 128x128, K staged 32, 8 warps (2x4), warp tile 64x32, pitch 80B.
// ---------------------------------------------------------------------------
#define TPITCH_B 80
#define TILE_B   (128 * TPITCH_B)
#define STAGE_B  (4 * TILE_B)
#define SM_GEMM_TOTAL (2 * STAGE_B)     // 81920

template <bool HILO>
__global__ __launch_bounds__(256, 1)
void gemm_mma(const __nv_bfloat16* __restrict__ Ah,
              const __nv_bfloat16* __restrict__ Al,
              const __nv_bfloat16* __restrict__ Bh,
              const __nv_bfloat16* __restrict__ Bl,
              float* __restrict__ C,
              __nv_bfloat16* __restrict__ Ch,
              __nv_bfloat16* __restrict__ Cl,
              float scale, int N) {
    extern __shared__ char smem[];
    const uint32_t sb = smem_u32(smem);
    const int tid  = threadIdx.x;
    const int wid  = tid >> 5;
    const int lane = tid & 31;
    const int warp_m = wid >> 2;
    const int warp_n = wid & 3;
    const int bx = blockIdx.x;
    const int by = blockIdx.y;

    const __nv_bfloat16* pAh = Ah + (size_t)(by * 128) * GK;
    const __nv_bfloat16* pAl = Al + (size_t)(by * 128) * GK;
    const __nv_bfloat16* pBh = Bh + (size_t)(bx * 128) * GK;
    const __nv_bfloat16* pBl = Bl + (size_t)(bx * 128) * GK;

    float acc[4][4][4];
#pragma unroll
    for (int i = 0; i < 4; i++)
#pragma unroll
        for (int j = 0; j < 4; j++)
#pragma unroll
            for (int v = 0; v < 4; v++) acc[i][j][v] = 0.f;

    const int r0 = (tid * 2) >> 2;
    const int c0 = (tid * 2) & 3;
    const int r1 = (tid * 2 + 1) >> 2;
    const int c1 = (tid * 2 + 1) & 3;

    auto issue_stage = [&](int buf, int k0) {
        const uint32_t s0 = sb + buf * STAGE_B;
        const size_t g0 = (size_t)r0 * GK + k0 + c0 * 8;
        const size_t g1 = (size_t)r1 * GK + k0 + c1 * 8;
        const uint32_t o0 = r0 * TPITCH_B + c0 * 16;
        const uint32_t o1 = r1 * TPITCH_B + c1 * 16;
        CP_ASYNC16(s0 + o0,              pAh + g0);
        CP_ASYNC16(s0 + o1,              pAh + g1);
        CP_ASYNC16(s0 + TILE_B + o0,     pAl + g0);
        CP_ASYNC16(s0 + TILE_B + o1,     pAl + g1);
        CP_ASYNC16(s0 + 2 * TILE_B + o0, pBh + g0);
        CP_ASYNC16(s0 + 2 * TILE_B + o1, pBh + g1);
        CP_ASYNC16(s0 + 3 * TILE_B + o0, pBl + g0);
        CP_ASYNC16(s0 + 3 * TILE_B + o1, pBl + g1);
        CP_COMMIT();
    };

    const uint32_t a_row = warp_m * 64 + (lane & 15);
    const uint32_t a_kof = (lane >> 4) * 8;
    const uint32_t b_row = warp_n * 32 + (lane & 7);
    const uint32_t b_kof = ((lane >> 3) & 1) * 8;

    issue_stage(0, 0);

    for (int ks = 0; ks < GK / 32; ks++) {
        const int buf = ks & 1;
        CP_WAIT_ALL();
        __syncthreads();
        if (ks + 1 < GK / 32) issue_stage(buf ^ 1, (ks + 1) * 32);

        const uint32_t s0 = sb + buf * STAGE_B;
#pragma unroll
        for (int pass = 0; pass < 3; pass++) {
            const uint32_t aoff = (pass == 2) ? TILE_B : 0;
            const uint32_t boff = (pass == 1) ? 3u * TILE_B : 2u * TILE_B;
#pragma unroll
            for (int kk = 0; kk < 32; kk += 16) {
                uint32_t afr[4][4], bfr[4][2];
#pragma unroll
                for (int mt = 0; mt < 4; mt++)
                    ldmatrix_x4(afr[mt],
                        s0 + aoff + (a_row + mt * 16) * TPITCH_B
                           + (kk + a_kof) * 2);
#pragma unroll
                for (int nt = 0; nt < 4; nt++)
                    ldmatrix_x2(bfr[nt],
                        s0 + boff + (b_row + nt * 8) * TPITCH_B
                           + (kk + b_kof) * 2);
#pragma unroll
                for (int mt = 0; mt < 4; mt++)
#pragma unroll
                    for (int nt = 0; nt < 4; nt++)
                        mma_16816(acc[mt][nt], afr[mt], bfr[nt]);
            }
        }
        __syncthreads();
    }

    const int crow = by * 128 + warp_m * 64 + (lane >> 2);
    const int ccol = bx * 128 + warp_n * 32 + (lane & 3) * 2;
#pragma unroll
    for (int mt = 0; mt < 4; mt++) {
#pragma unroll
        for (int nt = 0; nt < 4; nt++) {
            const size_t i0 = (size_t)(crow + mt * 16) * N + ccol + nt * 8;
            const size_t i1 = i0 + 8 * (size_t)N;
            if (HILO) {
                uint32_t h, l;
                split2(acc[mt][nt][0] * scale, acc[mt][nt][1] * scale, h, l);
                *(uint32_t*)(Ch + i0) = h;
                *(uint32_t*)(Cl + i0) = l;
                split2(acc[mt][nt][2] * scale, acc[mt][nt][3] * scale, h, l);
                *(uint32_t*)(Ch + i1) = h;
                *(uint32_t*)(Cl + i1) = l;
            } else {
                *(float2*)(C + i0) = make_float2(acc[mt][nt][0], acc[mt][nt][1]);
                *(float2*)(C + i1) = make_float2(acc[mt][nt][2], acc[mt][nt][3]);
            }
        }
    }
}

// ---------------------------------------------------------------------------
// fp32 -> (hi, lo) bf16 split, elementwise
// ---------------------------------------------------------------------------
__global__ void split_kernel(const float* __restrict__ s,
                             __nv_bfloat16* __restrict__ h,
                             __nv_bfloat16* __restrict__ l, int n4) {
    int i = blockIdx.x * blockDim.x + threadIdx.x;
    if (i >= n4) return;
    float4 v = ((const float4*)s)[i];
    uint32_t h0, l0, h1, l1;
    split2(v.x, v.y, h0, l0);
    split2(v.z, v.w, h1, l1);
    ((uint32_t*)h)[2 * i]     = h0;
    ((uint32_t*)h)[2 * i + 1] = h1;
    ((uint32_t*)l)[2 * i]     = l0;
    ((uint32_t*)l)[2 * i + 1] = l1;
}

// ---------------------------------------------------------------------------
// Transposed split: W fp32 [K, N] -> Wt hi/lo bf16 [N, K]
// ---------------------------------------------------------------------------
__global__ void splitT_kernel(const float* __restrict__ W,
                              __nv_bfloat16* __restrict__ th,
                              __nv_bfloat16* __restrict__ tl, int K, int N) {
    __shared__ float t[32][33];
    const int x0 = blockIdx.x * 32;
    const int y0 = blockIdx.y * 32;
    const int tx = threadIdx.x;
#pragma unroll
    for (int j = threadIdx.y; j < 32; j += 8)
        t[j][tx] = W[(size_t)(y0 + j) * N + x0 + tx];
    __syncthreads();
#pragma unroll
    for (int j = threadIdx.y; j < 32; j += 8) {
        float v = t[tx][j];
        size_t o = (size_t)(x0 + j) * K + y0 + tx;
        __nv_bfloat16 hv = __float2bfloat16(v);
        th[o] = hv;
        tl[o] = __float2bfloat16(v - __bfloat162float(hv));
    }
}

// ---------------------------------------------------------------------------
// flash_mma: HMMA flash attention with split-bf16 precision.
// grid (16 qtiles, 16 heads, 4 batch), 256 threads (8 warps x 16 q rows).
// kv tiles of 64, double-buffered cp.async. Q frags hoisted to registers.
// Writes attention output directly as bf16 hi/lo (feeds Wo GEMM).
// ---------------------------------------------------------------------------
#define FPITCH_B 144                    // 72 bf16
#define KTILE_B  (64 * FPITCH_B)        // 9216
#define FSTAGE_B (4 * KTILE_B)          // Kh Kl Vh Vl = 36864
#define SM_FLASH (2 * FSTAGE_B)         // 73728
#define NKTILES  (SEQ / 64)             // 32

__global__ __launch_bounds__(256, 1)
void flash_mma(const __nv_bfloat16* __restrict__ qh,
               const __nv_bfloat16* __restrict__ ql,
               const __nv_bfloat16* __restrict__ kvh,
               const __nv_bfloat16* __restrict__ kvl,
               __nv_bfloat16* __restrict__ oh,
               __nv_bfloat16* __restrict__ ol) {
    extern __shared__ char smem[];
    const uint32_t sb = smem_u32(smem);
    const int tid  = threadIdx.x;
    const int wid  = tid >> 5;
    const int lane = tid & 31;
    const int b = blockIdx.z;
    const int h = blockIdx.y;
    const int qbase = blockIdx.x * 128;
    const size_t browq = (size_t)(b * SEQ + qbase);
    const size_t brow  = (size_t)(b * SEQ);

    // ---- stage Q into buf1 area, and stage-0 K/V into buf0, concurrently
    {
        const uint32_t qh_s = sb + FSTAGE_B;           // 128 rows * 144B
        const uint32_t ql_s = qh_s + 128 * FPITCH_B;   // fits inside FSTAGE_B? no:
        // buf1 area = FSTAGE_B..2*FSTAGE_B (36864B); Qh 18432 + Ql 18432 = 36864 ✓
#pragma unroll
        for (int t = tid; t < 1024; t += 256) {
            const int r = t >> 3, c = t & 7;
            const size_t g = (browq + r) * DMODEL + h * DK + c * 8;
            CP_ASYNC16(qh_s + r * FPITCH_B + c * 16, qh + g);
            CP_ASYNC16(ql_s + r * FPITCH_B + c * 16, ql + g);
        }
        CP_COMMIT();
    }

    auto issue_kv = [&](int buf, int j0) {
        const uint32_t s0 = sb + buf * FSTAGE_B;
#pragma unroll
        for (int t = tid; t < 512; t += 256) {
            const int r = t >> 3, c = t & 7;
            const size_t g = (brow + j0 + r) * (2 * DMODEL) + h * DK + c * 8;
            const uint32_t o = r * FPITCH_B + c * 16;
            CP_ASYNC16(s0 + o,                kvh + g);
            CP_ASYNC16(s0 + KTILE_B + o,      kvl + g);
            CP_ASYNC16(s0 + 2 * KTILE_B + o,  kvh + g + DMODEL);
            CP_ASYNC16(s0 + 3 * KTILE_B + o,  kvl + g + DMODEL);
        }
        CP_COMMIT();
    };

    issue_kv(0, 0);
    CP_WAIT_ALL();
    __syncthreads();

    // ---- hoist Q fragments to registers
    uint32_t qa_h[4][4], qa_l[4][4];
    {
        const uint32_t a_row = wid * 16 + (lane & 15);
        const uint32_t a_kof = (lane >> 4) * 8;
        const uint32_t qh_s = sb + FSTAGE_B;
        const uint32_t ql_s = qh_s + 128 * FPITCH_B;
#pragma unroll
        for (int kc = 0; kc < 4; kc++) {
            ldmatrix_x4(qa_h[kc], qh_s + a_row * FPITCH_B + (kc * 16 + a_kof) * 2);
            ldmatrix_x4(qa_l[kc], ql_s + a_row * FPITCH_B + (kc * 16 + a_kof) * 2);
        }
    }
    __syncthreads();   // buf1 area now reusable

    float O[8][4];
#pragma unroll
    for (int i = 0; i < 8; i++)
#pragma unroll
        for (int j = 0; j < 4; j++) O[i][j] = 0.f;
    float m0 = -1e30f, m1 = -1e30f, l0 = 0.f, l1 = 0.f;

    const uint32_t k_lrow = (lane & 7);
    const uint32_t k_kof  = ((lane >> 3) & 1) * 8;
    const uint32_t v_lrow = (lane & 15);

    for (int jt = 0; jt < NKTILES; jt++) {
        const int buf = jt & 1;
        if (jt + 1 < NKTILES) {
            issue_kv(buf ^ 1, (jt + 1) * 64);
            CP_WAIT_ONE();
        } else {
            CP_WAIT_ALL();
        }
        __syncthreads();

        const uint32_t s0 = sb + buf * FSTAGE_B;

        // ---- S = Q K^T (3-pass split)
        float S[8][4];
#pragma unroll
        for (int i = 0; i < 8; i++)
#pragma unroll
            for (int j = 0; j < 4; j++) S[i][j] = 0.f;

#pragma unroll
        for (int kc = 0; kc < 4; kc++) {
#pragma unroll
            for (int nt = 0; nt < 8; nt++) {
                uint32_t bh[2], bl[2];
                const uint32_t ka = s0 + (nt * 8 + k_lrow) * FPITCH_B
                                  + (kc * 16 + k_kof) * 2;
                ldmatrix_x2(bh, ka);
                ldmatrix_x2(bl, ka + KTILE_B);
                mma_16816(S[nt], qa_h[kc], bh);
                mma_16816(S[nt], qa_h[kc], bl);
                mma_16816(S[nt], qa_l[kc], bh);
            }
        }

        // ---- online softmax
        float tm0 = -1e30f, tm1 = -1e30f;
#pragma unroll
        for (int nt = 0; nt < 8; nt++) {
            tm0 = fmaxf(tm0, fmaxf(S[nt][0], S[nt][1]));
            tm1 = fmaxf(tm1, fmaxf(S[nt][2], S[nt][3]));
        }
        tm0 = fmaxf(tm0, __shfl_xor_sync(0xffffffffu, tm0, 1));
        tm0 = fmaxf(tm0, __shfl_xor_sync(0xffffffffu, tm0, 2));
        tm1 = fmaxf(tm1, __shfl_xor_sync(0xffffffffu, tm1, 1));
        tm1 = fmaxf(tm1, __shfl_xor_sync(0xffffffffu, tm1, 2));

        const float mn0 = fmaxf(m0, tm0);
        const float mn1 = fmaxf(m1, tm1);
        const float cr0 = __expf(m0 - mn0);
        const float cr1 = __expf(m1 - mn1);
        l0 *= cr0;
        l1 *= cr1;
#pragma unroll
        for (int nt = 0; nt < 8; nt++) {
            O[nt][0] *= cr0; O[nt][1] *= cr0;
            O[nt][2] *= cr1; O[nt][3] *= cr1;
        }
#pragma unroll
        for (int nt = 0; nt < 8; nt++) {
            S[nt][0] = __expf(S[nt][0] - mn0);
            S[nt][1] = __expf(S[nt][1] - mn0);
            S[nt][2] = __expf(S[nt][2] - mn1);
            S[nt][3] = __expf(S[nt][3] - mn1);
            l0 += S[nt][0] + S[nt][1];
            l1 += S[nt][2] + S[nt][3];
        }
        m0 = mn0; m1 = mn1;

        // ---- O += P V (3-pass split; P C-frag -> A-frag in registers)
#pragma unroll
        for (int kc = 0; kc < 4; kc++) {
            uint32_t ah[4], al[4];
            split2(S[2 * kc][0],     S[2 * kc][1],     ah[0], al[0]);
            split2(S[2 * kc][2],     S[2 * kc][3],     ah[1], al[1]);
            split2(S[2 * kc + 1][0], S[2 * kc + 1][1], ah[2], al[2]);
            split2(S[2 * kc + 1][2], S[2 * kc + 1][3], ah[3], al[3]);
#pragma unroll
            for (int nd = 0; nd < 8; nd++) {
                uint32_t bvh[2], bvl[2];
                const uint32_t va = s0 + 2 * KTILE_B
                                  + (kc * 16 + v_lrow) * FPITCH_B + nd * 16;
                ldmatrix_x2_trans(bvh, va);
                ldmatrix_x2_trans(bvl, va + KTILE_B);
                mma_16816(O[nd], ah, bvh);
                mma_16816(O[nd], ah, bvl);
                mma_16816(O[nd], al, bvh);
            }
        }
        __syncthreads();
    }

    // ---- epilogue: reduce l across quad, normalize, write hi/lo bf16
    l0 += __shfl_xor_sync(0xffffffffu, l0, 1);
    l0 += __shfl_xor_sync(0xffffffffu, l0, 2);
    l1 += __shfl_xor_sync(0xffffffffu, l1, 1);
    l1 += __shfl_xor_sync(0xffffffffu, l1, 2);
    const float inv0 = 1.f / l0;
    const float inv1 = 1.f / l1;

    const int r0 = qbase + wid * 16 + (lane >> 2);
    const int r1 = r0 + 8;
    const int col = h * DK + (lane & 3) * 2;
#pragma unroll
    for (int nd = 0; nd < 8; nd++) {
        const size_t i0 = (brow + r0) * DMODEL + col + nd * 8;
        const size_t i1 = (brow + r1) * DMODEL + col + nd * 8;
        uint32_t hw, lw;
        split2(O[nd][0] * inv0, O[nd][1] * inv0, hw, lw);
        *(uint32_t*)(oh + i0) = hw;
        *(uint32_t*)(ol + i0) = lw;
        split2(O[nd][2] * inv1, O[nd][3] * inv1, hw, lw);
        *(uint32_t*)(oh + i1) = hw;
        *(uint32_t*)(ol + i1) = lw;
    }
}

// ---------------------------------------------------------------------------
extern "C" void kernel_launch(void* const* d_in, const int* in_sizes, int n_in,
                              void* d_out, int out_size) {
    const float* x   = (const float*)d_in[0];
    const float* Wq  = (const float*)d_in[1];
    const float* Wkv = (const float*)d_in[2];
    const float* Wo  = (const float*)d_in[3];
    float* out = (float*)d_out;

    __nv_bfloat16 *xh, *xl, *qh, *ql, *kvh, *kvl, *oh, *ol;
    __nv_bfloat16 *wqh, *wql, *wkvh, *wkvl, *woh, *wol;
    cudaGetSymbolAddress((void**)&xh,   g_xh);
    cudaGetSymbolAddress((void**)&xl,   g_xl);
    cudaGetSymbolAddress((void**)&qh,   g_qh);
    cudaGetSymbolAddress((void**)&ql,   g_ql);
    cudaGetSymbolAddress((void**)&kvh,  g_kvh);
    cudaGetSymbolAddress((void**)&kvl,  g_kvl);
    cudaGetSymbolAddress((void**)&oh,   g_oh);
    cudaGetSymbolAddress((void**)&ol,   g_ol);
    cudaGetSymbolAddress((void**)&wqh,  g_wq_h);
    cudaGetSymbolAddress((void**)&wql,  g_wq_l);
    cudaGetSymbolAddress((void**)&wkvh, g_wkv_h);
    cudaGetSymbolAddress((void**)&wkvl, g_wkv_l);
    cudaGetSymbolAddress((void**)&woh,  g_wo_h);
    cudaGetSymbolAddress((void**)&wol,  g_wo_l);

    cudaFuncSetAttribute(gemm_mma<true>,
        cudaFuncAttributeMaxDynamicSharedMemorySize, SM_GEMM_TOTAL);
    cudaFuncSetAttribute(gemm_mma<false>,
        cudaFuncAttributeMaxDynamicSharedMemorySize, SM_GEMM_TOTAL);
    cudaFuncSetAttribute(flash_mma,
        cudaFuncAttributeMaxDynamicSharedMemorySize, SM_FLASH);

    // 1) split input + weights
    {
        int n4 = ROWS * GK / 4;
        split_kernel<<<(n4 + 255) / 256, 256>>>(x, xh, xl, n4);
    }
    splitT_kernel<<<dim3(DMODEL / 32, GK / 32), dim3(32, 8)>>>(Wq, wqh, wql, GK, DMODEL);
    splitT_kernel<<<dim3(2 * DMODEL / 32, GK / 32), dim3(32, 8)>>>(Wkv, wkvh, wkvl, GK, 2 * DMODEL);
    splitT_kernel<<<dim3(DMODEL / 32, GK / 32), dim3(32, 8)>>>(Wo, woh, wol, GK, DMODEL);

    // 2) projections (hi/lo epilogue; Q pre-scaled by 1/sqrt(dk))
    gemm_mma<true><<<dim3(DMODEL / 128, ROWS / 128), 256, SM_GEMM_TOTAL>>>(
        xh, xl, wqh, wql, nullptr, qh, ql, 0.125f, DMODEL);
    gemm_mma<true><<<dim3(2 * DMODEL / 128, ROWS / 128), 256, SM_GEMM_TOTAL>>>(
        xh, xl, wkvh, wkvl, nullptr, kvh, kvl, 1.0f, 2 * DMODEL);

    // 3) attention on tensor cores
    flash_mma<<<dim3(SEQ / 128, NHEADS, BATCH), 256, SM_FLASH>>>(
        qh, ql, kvh, kvl, oh, ol);

    // 4) output projection (fp32 epilogue)
    gemm_mma<false><<<dim3(DMODEL / 128, ROWS / 128), 256, SM_GEMM_TOTAL>>>(
        oh, ol, woh, wol, out, nullptr, nullptr, 1.0f, DMODEL);
}

// round 5
// speedup vs baseline: 7.0577x; 1.4167x over previous
#include <cuda_runtime.h>
#include <cuda_fp16.h>
#include <cstdint>
#include <math.h>

#define BATCH  4
#define SEQ    2048
#define NHEADS 16
#define DK     64
#define DMODEL 1024
#define ROWS   (BATCH * SEQ)   // 8192
#define GK     1024

// ---------------------------------------------------------------------------
// Scratch (static device globals)
// ---------------------------------------------------------------------------
__device__ __half g_xh[ROWS * GK];
__device__ __half g_xl[ROWS * GK];
__device__ __half g_qh[ROWS * DMODEL];        // Q proj hi (pre-scaled)
__device__ __half g_ql[ROWS * DMODEL];
__device__ __half g_kv[ROWS * 2 * DMODEL];    // KV proj, single fp16
__device__ __half g_oh[ROWS * DMODEL];        // attention out hi
__device__ __half g_ol[ROWS * DMODEL];
__device__ __half g_wq[DMODEL * GK];          // transposed weights [N,K], single fp16
__device__ __half g_wkv[2 * DMODEL * GK];
__device__ __half g_wo[DMODEL * GK];

// ---------------------------------------------------------------------------
// helpers
// ---------------------------------------------------------------------------
__device__ __forceinline__ uint32_t smem_u32(const void* p) {
    uint32_t a;
    asm("{ .reg .u64 t; cvta.to.shared.u64 t, %1; cvt.u32.u64 %0, t; }"
        : "=r"(a) : "l"(p));
    return a;
}

#define CP_ASYNC16(dst, src) \
    asm volatile("cp.async.cg.shared.global [%0], [%1], 16;" \
                 :: "r"(dst), "l"(src) : "memory")
#define CP_COMMIT()   asm volatile("cp.async.commit_group;" ::: "memory")
#define CP_WAIT_ALL() asm volatile("cp.async.wait_group 0;" ::: "memory")
#define CP_WAIT_ONE() asm volatile("cp.async.wait_group 1;" ::: "memory")

__device__ __forceinline__ void ldmatrix_x4(uint32_t* r, uint32_t addr) {
    asm volatile("ldmatrix.sync.aligned.m8n8.x4.shared.b16 {%0,%1,%2,%3}, [%4];"
                 : "=r"(r[0]), "=r"(r[1]), "=r"(r[2]), "=r"(r[3]) : "r"(addr));
}
__device__ __forceinline__ void ldmatrix_x2(uint32_t* r, uint32_t addr) {
    asm volatile("ldmatrix.sync.aligned.m8n8.x2.shared.b16 {%0,%1}, [%2];"
                 : "=r"(r[0]), "=r"(r[1]) : "r"(addr));
}
__device__ __forceinline__ void ldmatrix_x2_trans(uint32_t* r, uint32_t addr) {
    asm volatile("ldmatrix.sync.aligned.m8n8.x2.trans.shared.b16 {%0,%1}, [%2];"
                 : "=r"(r[0]), "=r"(r[1]) : "r"(addr));
}
__device__ __forceinline__ void mma_16816(float* c, const uint32_t* a,
                                          const uint32_t* b) {
    asm volatile(
        "mma.sync.aligned.m16n8k16.row.col.f32.f16.f16.f32 "
        "{%0,%1,%2,%3}, {%4,%5,%6,%7}, {%8,%9}, {%0,%1,%2,%3};"
        : "+f"(c[0]), "+f"(c[1]), "+f"(c[2]), "+f"(c[3])
        : "r"(a[0]), "r"(a[1]), "r"(a[2]), "r"(a[3]), "r"(b[0]), "r"(b[1]));
}

// pack (p0, p1) into fp16x2 hi word + fp16x2 lo-residual word
__device__ __forceinline__ void split2(float p0, float p1,
                                       uint32_t& h, uint32_t& l) {
    __half2 hh = __floats2half2_rn(p0, p1);
    float2 hf = __half22float2(hh);
    __half2 ll = __floats2half2_rn(p0 - hf.x, p1 - hf.y);
    h = *(uint32_t*)&hh;
    l = *(uint32_t*)&ll;
}

// ---------------------------------------------------------------------------
// split-fp16 HMMA GEMM (2-pass): C = A @ W^T
//   A [M,GK] as Ah/Al fp16 hi/lo, W transposed [N,GK] single fp16.
//   C = Ah·B^T + Al·B^T  (A exact to ~2^-23, B repr err ~2^-12)
// OUT: 0 -> fp32 C, 1 -> Ch/Cl fp16 hi/lo (scaled), 2 -> Ch single fp16
// CTA 128x128, K staged 32, 3-stage cp.async pipeline, 8 warps (2x4).
// ---------------------------------------------------------------------------
#define TPITCH_B 80
#define TILE_B   (128 * TPITCH_B)       // 10240
#define STAGE_B  (3 * TILE_B)           // Ah, Al, B = 30720
#define SM_GEMM_TOTAL (3 * STAGE_B)     // 92160
#define NKS (GK / 32)                   // 32

template <int OUT>
__global__ __launch_bounds__(256, 1)
void gemm_mma(const __half* __restrict__ Ah,
              const __half* __restrict__ Al,
              const __half* __restrict__ B,
              float* __restrict__ C,
              __half* __restrict__ Ch,
              __half* __restrict__ Cl,
              float scale, int N) {
    extern __shared__ char smem[];
    const uint32_t sb = smem_u32(smem);
    const int tid  = threadIdx.x;
    const int wid  = tid >> 5;
    const int lane = tid & 31;
    const int warp_m = wid >> 2;
    const int warp_n = wid & 3;
    const int bx = blockIdx.x;
    const int by = blockIdx.y;

    const __half* pAh = Ah + (size_t)(by * 128) * GK;
    const __half* pAl = Al + (size_t)(by * 128) * GK;
    const __half* pB  = B  + (size_t)(bx * 128) * GK;

    float acc[4][4][4];
#pragma unroll
    for (int i = 0; i < 4; i++)
#pragma unroll
        for (int j = 0; j < 4; j++)
#pragma unroll
            for (int v = 0; v < 4; v++) acc[i][j][v] = 0.f;

    const int r0 = (tid * 2) >> 2;
    const int c0 = (tid * 2) & 3;
    const int r1 = (tid * 2 + 1) >> 2;
    const int c1 = (tid * 2 + 1) & 3;

    auto issue_stage = [&](int buf, int k0) {
        const uint32_t s0 = sb + buf * STAGE_B;
        const size_t g0 = (size_t)r0 * GK + k0 + c0 * 8;
        const size_t g1 = (size_t)r1 * GK + k0 + c1 * 8;
        const uint32_t o0 = r0 * TPITCH_B + c0 * 16;
        const uint32_t o1 = r1 * TPITCH_B + c1 * 16;
        CP_ASYNC16(s0 + o0,              pAh + g0);
        CP_ASYNC16(s0 + o1,              pAh + g1);
        CP_ASYNC16(s0 + TILE_B + o0,     pAl + g0);
        CP_ASYNC16(s0 + TILE_B + o1,     pAl + g1);
        CP_ASYNC16(s0 + 2 * TILE_B + o0, pB + g0);
        CP_ASYNC16(s0 + 2 * TILE_B + o1, pB + g1);
        CP_COMMIT();
    };

    const uint32_t a_row = warp_m * 64 + (lane & 15);
    const uint32_t a_kof = (lane >> 4) * 8;
    const uint32_t b_row = warp_n * 32 + (lane & 7);
    const uint32_t b_kof = ((lane >> 3) & 1) * 8;

    issue_stage(0, 0);
    issue_stage(1, 32);

    for (int ks = 0; ks < NKS; ks++) {
        const int buf = ks % 3;
        CP_WAIT_ONE();
        __syncthreads();
        if (ks + 2 < NKS) issue_stage((ks + 2) % 3, (ks + 2) * 32);
        else CP_COMMIT();   // empty group keeps wait_group 1 math correct

        const uint32_t s0 = sb + buf * STAGE_B;
#pragma unroll
        for (int pass = 0; pass < 2; pass++) {
            const uint32_t aoff = pass ? TILE_B : 0u;
            const uint32_t boff = 2u * TILE_B;
#pragma unroll
            for (int kk = 0; kk < 32; kk += 16) {
                uint32_t afr[4][4], bfr[4][2];
#pragma unroll
                for (int mt = 0; mt < 4; mt++)
                    ldmatrix_x4(afr[mt],
                        s0 + aoff + (a_row + mt * 16) * TPITCH_B
                           + (kk + a_kof) * 2);
#pragma unroll
                for (int nt = 0; nt < 4; nt++)
                    ldmatrix_x2(bfr[nt],
                        s0 + boff + (b_row + nt * 8) * TPITCH_B
                           + (kk + b_kof) * 2);
#pragma unroll
                for (int mt = 0; mt < 4; mt++)
#pragma unroll
                    for (int nt = 0; nt < 4; nt++)
                        mma_16816(acc[mt][nt], afr[mt], bfr[nt]);
            }
        }
    }

    __syncthreads();
    const int crow = by * 128 + warp_m * 64 + (lane >> 2);
    const int ccol = bx * 128 + warp_n * 32 + (lane & 3) * 2;
#pragma unroll
    for (int mt = 0; mt < 4; mt++) {
#pragma unroll
        for (int nt = 0; nt < 4; nt++) {
            const size_t i0 = (size_t)(crow + mt * 16) * N + ccol + nt * 8;
            const size_t i1 = i0 + 8 * (size_t)N;
            if (OUT == 1) {
                uint32_t h, l;
                split2(acc[mt][nt][0] * scale, acc[mt][nt][1] * scale, h, l);
                *(uint32_t*)(Ch + i0) = h;
                *(uint32_t*)(Cl + i0) = l;
                split2(acc[mt][nt][2] * scale, acc[mt][nt][3] * scale, h, l);
                *(uint32_t*)(Ch + i1) = h;
                *(uint32_t*)(Cl + i1) = l;
            } else if (OUT == 2) {
                __half2 v0 = __floats2half2_rn(acc[mt][nt][0], acc[mt][nt][1]);
                __half2 v1 = __floats2half2_rn(acc[mt][nt][2], acc[mt][nt][3]);
                *(__half2*)(Ch + i0) = v0;
                *(__half2*)(Ch + i1) = v1;
            } else {
                *(float2*)(C + i0) = make_float2(acc[mt][nt][0], acc[mt][nt][1]);
                *(float2*)(C + i1) = make_float2(acc[mt][nt][2], acc[mt][nt][3]);
            }
        }
    }
}

// ---------------------------------------------------------------------------
// fp32 -> (hi, lo) fp16 split, elementwise
// ---------------------------------------------------------------------------
__global__ void split_kernel(const float* __restrict__ s,
                             __half* __restrict__ h,
                             __half* __restrict__ l, int n4) {
    int i = blockIdx.x * blockDim.x + threadIdx.x;
    if (i >= n4) return;
    float4 v = ((const float4*)s)[i];
    uint32_t h0, l0, h1, l1;
    split2(v.x, v.y, h0, l0);
    split2(v.z, v.w, h1, l1);
    ((uint32_t*)h)[2 * i]     = h0;
    ((uint32_t*)h)[2 * i + 1] = h1;
    ((uint32_t*)l)[2 * i]     = l0;
    ((uint32_t*)l)[2 * i + 1] = l1;
}

// ---------------------------------------------------------------------------
// Transposed single-fp16: W fp32 [K, N] -> Wt fp16 [N, K]
// ---------------------------------------------------------------------------
__global__ void splitT_kernel(const float* __restrict__ W,
                              __half* __restrict__ th, int K, int N) {
    __shared__ float t[32][33];
    const int x0 = blockIdx.x * 32;
    const int y0 = blockIdx.y * 32;
    const int tx = threadIdx.x;
#pragma unroll
    for (int j = threadIdx.y; j < 32; j += 8)
        t[j][tx] = W[(size_t)(y0 + j) * N + x0 + tx];
    __syncthreads();
#pragma unroll
    for (int j = threadIdx.y; j < 32; j += 8)
        th[(size_t)(x0 + j) * K + y0 + tx] = __float2half_rn(t[tx][j]);
}

// ---------------------------------------------------------------------------
// flash_mma: HMMA flash attention, fp16 2-pass split.
// Q hi/lo (left operand, exact); K,V single fp16.
// grid (16 qtiles, 16 heads, 4 batch), 256 threads (8 warps x 16 q rows).
// ---------------------------------------------------------------------------
#define FPITCH_B 144                    // 72 halves
#define KTILE_B  (64 * FPITCH_B)        // 9216
#define FSTAGE_B (2 * KTILE_B)          // K + V = 18432
#define FQ_B     (2 * 128 * FPITCH_B)   // Qh + Ql = 36864
#define SM_FLASH (2 * FSTAGE_B + FQ_B)  // 73728
#define NKTILES  (SEQ / 64)             // 32

__global__ __launch_bounds__(256, 1)
void flash_mma(const __half* __restrict__ qh,
               const __half* __restrict__ ql,
               const __half* __restrict__ kv,
               __half* __restrict__ oh,
               __half* __restrict__ ol) {
    extern __shared__ char smem[];
    const uint32_t sb = smem_u32(smem);
    const int tid  = threadIdx.x;
    const int wid  = tid >> 5;
    const int lane = tid & 31;
    const int b = blockIdx.z;
    const int h = blockIdx.y;
    const int qbase = blockIdx.x * 128;
    const size_t browq = (size_t)(b * SEQ + qbase);
    const size_t brow  = (size_t)(b * SEQ);

    const uint32_t qh_s = sb + 2 * FSTAGE_B;
    const uint32_t ql_s = qh_s + 128 * FPITCH_B;

    // stage Q (hi+lo)
#pragma unroll
    for (int t = tid; t < 1024; t += 256) {
        const int r = t >> 3, c = t & 7;
        const size_t g = (browq + r) * DMODEL + h * DK + c * 8;
        CP_ASYNC16(qh_s + r * FPITCH_B + c * 16, qh + g);
        CP_ASYNC16(ql_s + r * FPITCH_B + c * 16, ql + g);
    }
    CP_COMMIT();

    auto issue_kv = [&](int buf, int j0) {
        const uint32_t s0 = sb + buf * FSTAGE_B;
#pragma unroll
        for (int t = tid; t < 512; t += 256) {
            const int r = t >> 3, c = t & 7;
            const size_t g = (brow + j0 + r) * (2 * DMODEL) + h * DK + c * 8;
            const uint32_t o = r * FPITCH_B + c * 16;
            CP_ASYNC16(s0 + o,           kv + g);            // K
            CP_ASYNC16(s0 + KTILE_B + o, kv + g + DMODEL);   // V
        }
        CP_COMMIT();
    };

    issue_kv(0, 0);
    CP_WAIT_ALL();
    __syncthreads();

    // hoist Q fragments to registers
    uint32_t qa_h[4][4], qa_l[4][4];
    {
        const uint32_t a_row = wid * 16 + (lane & 15);
        const uint32_t a_kof = (lane >> 4) * 8;
#pragma unroll
        for (int kc = 0; kc < 4; kc++) {
            ldmatrix_x4(qa_h[kc], qh_s + a_row * FPITCH_B + (kc * 16 + a_kof) * 2);
            ldmatrix_x4(qa_l[kc], ql_s + a_row * FPITCH_B + (kc * 16 + a_kof) * 2);
        }
    }

    float O[8][4];
#pragma unroll
    for (int i = 0; i < 8; i++)
#pragma unroll
        for (int j = 0; j < 4; j++) O[i][j] = 0.f;
    float m0 = -1e30f, m1 = -1e30f, l0 = 0.f, l1 = 0.f;

    const uint32_t k_lrow = (lane & 7);
    const uint32_t k_kof  = ((lane >> 3) & 1) * 8;
    const uint32_t v_lrow = (lane & 15);

    for (int jt = 0; jt < NKTILES; jt++) {
        const int buf = jt & 1;
        if (jt + 1 < NKTILES) {
            issue_kv(buf ^ 1, (jt + 1) * 64);
            CP_WAIT_ONE();
        } else {
            CP_WAIT_ALL();
        }
        __syncthreads();

        const uint32_t s0 = sb + buf * FSTAGE_B;

        // ---- S = Q K^T (2-pass: Qh·K + Ql·K)
        float S[8][4];
#pragma unroll
        for (int i = 0; i < 8; i++)
#pragma unroll
            for (int j = 0; j < 4; j++) S[i][j] = 0.f;

#pragma unroll
        for (int kc = 0; kc < 4; kc++) {
#pragma unroll
            for (int nt = 0; nt < 8; nt++) {
                uint32_t bh[2];
                ldmatrix_x2(bh, s0 + (nt * 8 + k_lrow) * FPITCH_B
                                + (kc * 16 + k_kof) * 2);
                mma_16816(S[nt], qa_h[kc], bh);
                mma_16816(S[nt], qa_l[kc], bh);
            }
        }

        // ---- online softmax
        float tm0 = -1e30f, tm1 = -1e30f;
#pragma unroll
        for (int nt = 0; nt < 8; nt++) {
            tm0 = fmaxf(tm0, fmaxf(S[nt][0], S[nt][1]));
            tm1 = fmaxf(tm1, fmaxf(S[nt][2], S[nt][3]));
        }
        tm0 = fmaxf(tm0, __shfl_xor_sync(0xffffffffu, tm0, 1));
        tm0 = fmaxf(tm0, __shfl_xor_sync(0xffffffffu, tm0, 2));
        tm1 = fmaxf(tm1, __shfl_xor_sync(0xffffffffu, tm1, 1));
        tm1 = fmaxf(tm1, __shfl_xor_sync(0xffffffffu, tm1, 2));

        const float mn0 = fmaxf(m0, tm0);
        const float mn1 = fmaxf(m1, tm1);
        const float cr0 = __expf(m0 - mn0);
        const float cr1 = __expf(m1 - mn1);
        l0 *= cr0;
        l1 *= cr1;
#pragma unroll
        for (int nt = 0; nt < 8; nt++) {
            O[nt][0] *= cr0; O[nt][1] *= cr0;
            O[nt][2] *= cr1; O[nt][3] *= cr1;
        }
#pragma unroll
        for (int nt = 0; nt < 8; nt++) {
            S[nt][0] = __expf(S[nt][0] - mn0);
            S[nt][1] = __expf(S[nt][1] - mn0);
            S[nt][2] = __expf(S[nt][2] - mn1);
            S[nt][3] = __expf(S[nt][3] - mn1);
            l0 += S[nt][0] + S[nt][1];
            l1 += S[nt][2] + S[nt][3];
        }
        m0 = mn0; m1 = mn1;

        // ---- O += P V (2-pass: Ph·V + Pl·V; V single fp16)
#pragma unroll
        for (int kc = 0; kc < 4; kc++) {
            uint32_t ah[4], al[4];
            split2(S[2 * kc][0],     S[2 * kc][1],     ah[0], al[0]);
            split2(S[2 * kc][2],     S[2 * kc][3],     ah[1], al[1]);
            split2(S[2 * kc + 1][0], S[2 * kc + 1][1], ah[2], al[2]);
            split2(S[2 * kc + 1][2], S[2 * kc + 1][3], ah[3], al[3]);
#pragma unroll
            for (int nd = 0; nd < 8; nd++) {
                uint32_t bv[2];
                ldmatrix_x2_trans(bv, s0 + KTILE_B
                                  + (kc * 16 + v_lrow) * FPITCH_B + nd * 16);
                mma_16816(O[nd], ah, bv);
                mma_16816(O[nd], al, bv);
            }
        }
        __syncthreads();
    }

    // ---- epilogue
    l0 += __shfl_xor_sync(0xffffffffu, l0, 1);
    l0 += __shfl_xor_sync(0xffffffffu, l0, 2);
    l1 += __shfl_xor_sync(0xffffffffu, l1, 1);
    l1 += __shfl_xor_sync(0xffffffffu, l1, 2);
    const float inv0 = 1.f / l0;
    const float inv1 = 1.f / l1;

    const int r0 = qbase + wid * 16 + (lane >> 2);
    const int r1 = r0 + 8;
    const int col = h * DK + (lane & 3) * 2;
#pragma unroll
    for (int nd = 0; nd < 8; nd++) {
        const size_t i0 = (brow + r0) * DMODEL + col + nd * 8;
        const size_t i1 = (brow + r1) * DMODEL + col + nd * 8;
        uint32_t hw, lw;
        split2(O[nd][0] * inv0, O[nd][1] * inv0, hw, lw);
        *(uint32_t*)(oh + i0) = hw;
        *(uint32_t*)(ol + i0) = lw;
        split2(O[nd][2] * inv1, O[nd][3] * inv1, hw, lw);
        *(uint32_t*)(oh + i1) = hw;
        *(uint32_t*)(ol + i1) = lw;
    }
}

// ---------------------------------------------------------------------------
extern "C" void kernel_launch(void* const* d_in, const int* in_sizes, int n_in,
                              void* d_out, int out_size) {
    const float* x   = (const float*)d_in[0];
    const float* Wq  = (const float*)d_in[1];
    const float* Wkv = (const float*)d_in[2];
    const float* Wo  = (const float*)d_in[3];
    float* out = (float*)d_out;

    __half *xh, *xl, *qh, *ql, *kv, *oh, *ol, *wq, *wkv, *wo;
    cudaGetSymbolAddress((void**)&xh,  g_xh);
    cudaGetSymbolAddress((void**)&xl,  g_xl);
    cudaGetSymbolAddress((void**)&qh,  g_qh);
    cudaGetSymbolAddress((void**)&ql,  g_ql);
    cudaGetSymbolAddress((void**)&kv,  g_kv);
    cudaGetSymbolAddress((void**)&oh,  g_oh);
    cudaGetSymbolAddress((void**)&ol,  g_ol);
    cudaGetSymbolAddress((void**)&wq,  g_wq);
    cudaGetSymbolAddress((void**)&wkv, g_wkv);
    cudaGetSymbolAddress((void**)&wo,  g_wo);

    cudaFuncSetAttribute(gemm_mma<0>,
        cudaFuncAttributeMaxDynamicSharedMemorySize, SM_GEMM_TOTAL);
    cudaFuncSetAttribute(gemm_mma<1>,
        cudaFuncAttributeMaxDynamicSharedMemorySize, SM_GEMM_TOTAL);
    cudaFuncSetAttribute(gemm_mma<2>,
        cudaFuncAttributeMaxDynamicSharedMemorySize, SM_GEMM_TOTAL);
    cudaFuncSetAttribute(flash_mma,
        cudaFuncAttributeMaxDynamicSharedMemorySize, SM_FLASH);

    // 1) split input (hi/lo) + transpose weights (single fp16)
    {
        int n4 = ROWS * GK / 4;
        split_kernel<<<(n4 + 255) / 256, 256>>>(x, xh, xl, n4);
    }
    splitT_kernel<<<dim3(DMODEL / 32, GK / 32), dim3(32, 8)>>>(Wq, wq, GK, DMODEL);
    splitT_kernel<<<dim3(2 * DMODEL / 32, GK / 32), dim3(32, 8)>>>(Wkv, wkv, GK, 2 * DMODEL);
    splitT_kernel<<<dim3(DMODEL / 32, GK / 32), dim3(32, 8)>>>(Wo, wo, GK, DMODEL);

    // 2) projections: Q -> hi/lo (pre-scaled), KV -> single fp16
    gemm_mma<1><<<dim3(DMODEL / 128, ROWS / 128), 256, SM_GEMM_TOTAL>>>(
        xh, xl, wq, nullptr, qh, ql, 0.125f, DMODEL);
    gemm_mma<2><<<dim3(2 * DMODEL / 128, ROWS / 128), 256, SM_GEMM_TOTAL>>>(
        xh, xl, wkv, nullptr, kv, nullptr, 1.0f, 2 * DMODEL);

    // 3) attention on tensor cores
    flash_mma<<<dim3(SEQ / 128, NHEADS, BATCH), 256, SM_FLASH>>>(
        qh, ql, kv, oh, ol);

    // 4) output projection (fp32 epilogue)
    gemm_mma<0><<<dim3(DMODEL / 128, ROWS / 128), 256, SM_GEMM_TOTAL>>>(
        oh, ol, wo, out, nullptr, nullptr, 1.0f, DMODEL);
}

// round 6
// speedup vs baseline: 7.7307x; 1.0954x over previous
#include <cuda_runtime.h>
#include <cuda_fp16.h>
#include <cstdint>
#include <math.h>

#define BATCH  4
#define SEQ    2048
#define NHEADS 16
#define DK     64
#define DMODEL 1024
#define ROWS   (BATCH * SEQ)   // 8192
#define GK     1024

// ---------------------------------------------------------------------------
// Scratch (static device globals)
// ---------------------------------------------------------------------------
__device__ __half g_xh[ROWS * GK];
__device__ __half g_xl[ROWS * GK];
__device__ __half g_qh[ROWS * DMODEL];        // Q proj hi (pre-scaled)
__device__ __half g_ql[ROWS * DMODEL];
__device__ __half g_kv[ROWS * 2 * DMODEL];    // KV proj, single fp16
__device__ __half g_oh[ROWS * DMODEL];        // attention out hi
__device__ __half g_ol[ROWS * DMODEL];
__device__ __half g_wq[DMODEL * GK];          // transposed weights [N,K], single fp16
__device__ __half g_wkv[2 * DMODEL * GK];
__device__ __half g_wo[DMODEL * GK];

// ---------------------------------------------------------------------------
// helpers
// ---------------------------------------------------------------------------
__device__ __forceinline__ uint32_t smem_u32(const void* p) {
    uint32_t a;
    asm("{ .reg .u64 t; cvta.to.shared.u64 t, %1; cvt.u32.u64 %0, t; }"
        : "=r"(a) : "l"(p));
    return a;
}

#define CP_ASYNC16(dst, src) \
    asm volatile("cp.async.cg.shared.global [%0], [%1], 16;" \
                 :: "r"(dst), "l"(src) : "memory")
#define CP_COMMIT()   asm volatile("cp.async.commit_group;" ::: "memory")
#define CP_WAIT_ALL() asm volatile("cp.async.wait_group 0;" ::: "memory")
#define CP_WAIT_ONE() asm volatile("cp.async.wait_group 1;" ::: "memory")

__device__ __forceinline__ void ldmatrix_x4(uint32_t* r, uint32_t addr) {
    asm volatile("ldmatrix.sync.aligned.m8n8.x4.shared.b16 {%0,%1,%2,%3}, [%4];"
                 : "=r"(r[0]), "=r"(r[1]), "=r"(r[2]), "=r"(r[3]) : "r"(addr));
}
__device__ __forceinline__ void ldmatrix_x2(uint32_t* r, uint32_t addr) {
    asm volatile("ldmatrix.sync.aligned.m8n8.x2.shared.b16 {%0,%1}, [%2];"
                 : "=r"(r[0]), "=r"(r[1]) : "r"(addr));
}
__device__ __forceinline__ void ldmatrix_x2_trans(uint32_t* r, uint32_t addr) {
    asm volatile("ldmatrix.sync.aligned.m8n8.x2.trans.shared.b16 {%0,%1}, [%2];"
                 : "=r"(r[0]), "=r"(r[1]) : "r"(addr));
}
__device__ __forceinline__ void mma_16816(float* c, const uint32_t* a,
                                          const uint32_t* b) {
    asm volatile(
        "mma.sync.aligned.m16n8k16.row.col.f32.f16.f16.f32 "
        "{%0,%1,%2,%3}, {%4,%5,%6,%7}, {%8,%9}, {%0,%1,%2,%3};"
        : "+f"(c[0]), "+f"(c[1]), "+f"(c[2]), "+f"(c[3])
        : "r"(a[0]), "r"(a[1]), "r"(a[2]), "r"(a[3]), "r"(b[0]), "r"(b[1]));
}

// pack (p0, p1) into fp16x2 hi word + fp16x2 lo-residual word
__device__ __forceinline__ void split2(float p0, float p1,
                                       uint32_t& h, uint32_t& l) {
    __half2 hh = __floats2half2_rn(p0, p1);
    float2 hf = __half22float2(hh);
    __half2 ll = __floats2half2_rn(p0 - hf.x, p1 - hf.y);
    h = *(uint32_t*)&hh;
    l = *(uint32_t*)&ll;
}

// ---------------------------------------------------------------------------
// split-fp16 HMMA GEMM (2-pass): C = A @ W^T
//   A [M,GK] as Ah/Al fp16 hi/lo, W transposed [N,GK] single fp16.
// OUT: 0 -> fp32 C, 1 -> Ch/Cl fp16 hi/lo (scaled), 2 -> Ch single fp16
// CTA 128x128, K staged 32, 2-stage cp.async pipeline, 8 warps (2x4).
// smem 61440 -> 2 CTAs/SM.
// ---------------------------------------------------------------------------
#define TPITCH_B 80
#define TILE_B   (128 * TPITCH_B)       // 10240
#define STAGE_B  (3 * TILE_B)           // Ah, Al, B = 30720
#define SM_GEMM_TOTAL (2 * STAGE_B)     // 61440
#define NKS (GK / 32)                   // 32

template <int OUT>
__global__ __launch_bounds__(256, 2)
void gemm_mma(const __half* __restrict__ Ah,
              const __half* __restrict__ Al,
              const __half* __restrict__ B,
              float* __restrict__ C,
              __half* __restrict__ Ch,
              __half* __restrict__ Cl,
              float scale, int N) {
    extern __shared__ char smem[];
    const uint32_t sb = smem_u32(smem);
    const int tid  = threadIdx.x;
    const int wid  = tid >> 5;
    const int lane = tid & 31;
    const int warp_m = wid >> 2;
    const int warp_n = wid & 3;
    const int bx = blockIdx.x;
    const int by = blockIdx.y;

    const __half* pAh = Ah + (size_t)(by * 128) * GK;
    const __half* pAl = Al + (size_t)(by * 128) * GK;
    const __half* pB  = B  + (size_t)(bx * 128) * GK;

    float acc[4][4][4];
#pragma unroll
    for (int i = 0; i < 4; i++)
#pragma unroll
        for (int j = 0; j < 4; j++)
#pragma unroll
            for (int v = 0; v < 4; v++) acc[i][j][v] = 0.f;

    const int r0 = (tid * 2) >> 2;
    const int c0 = (tid * 2) & 3;
    const int r1 = (tid * 2 + 1) >> 2;
    const int c1 = (tid * 2 + 1) & 3;

    auto issue_stage = [&](int buf, int k0) {
        const uint32_t s0 = sb + buf * STAGE_B;
        const size_t g0 = (size_t)r0 * GK + k0 + c0 * 8;
        const size_t g1 = (size_t)r1 * GK + k0 + c1 * 8;
        const uint32_t o0 = r0 * TPITCH_B + c0 * 16;
        const uint32_t o1 = r1 * TPITCH_B + c1 * 16;
        CP_ASYNC16(s0 + o0,              pAh + g0);
        CP_ASYNC16(s0 + o1,              pAh + g1);
        CP_ASYNC16(s0 + TILE_B + o0,     pAl + g0);
        CP_ASYNC16(s0 + TILE_B + o1,     pAl + g1);
        CP_ASYNC16(s0 + 2 * TILE_B + o0, pB + g0);
        CP_ASYNC16(s0 + 2 * TILE_B + o1, pB + g1);
        CP_COMMIT();
    };

    const uint32_t a_row = warp_m * 64 + (lane & 15);
    const uint32_t a_kof = (lane >> 4) * 8;
    const uint32_t b_row = warp_n * 32 + (lane & 7);
    const uint32_t b_kof = ((lane >> 3) & 1) * 8;

    issue_stage(0, 0);

    for (int ks = 0; ks < NKS; ks++) {
        const int buf = ks & 1;
        CP_WAIT_ALL();
        __syncthreads();
        if (ks + 1 < NKS) issue_stage(buf ^ 1, (ks + 1) * 32);

        const uint32_t s0 = sb + buf * STAGE_B;
#pragma unroll
        for (int pass = 0; pass < 2; pass++) {
            const uint32_t aoff = pass ? TILE_B : 0u;
            const uint32_t boff = 2u * TILE_B;
#pragma unroll
            for (int kk = 0; kk < 32; kk += 16) {
                uint32_t afr[4][4], bfr[4][2];
#pragma unroll
                for (int mt = 0; mt < 4; mt++)
                    ldmatrix_x4(afr[mt],
                        s0 + aoff + (a_row + mt * 16) * TPITCH_B
                           + (kk + a_kof) * 2);
#pragma unroll
                for (int nt = 0; nt < 4; nt++)
                    ldmatrix_x2(bfr[nt],
                        s0 + boff + (b_row + nt * 8) * TPITCH_B
                           + (kk + b_kof) * 2);
#pragma unroll
                for (int mt = 0; mt < 4; mt++)
#pragma unroll
                    for (int nt = 0; nt < 4; nt++)
                        mma_16816(acc[mt][nt], afr[mt], bfr[nt]);
            }
        }
    }

    __syncthreads();
    const int crow = by * 128 + warp_m * 64 + (lane >> 2);
    const int ccol = bx * 128 + warp_n * 32 + (lane & 3) * 2;
#pragma unroll
    for (int mt = 0; mt < 4; mt++) {
#pragma unroll
        for (int nt = 0; nt < 4; nt++) {
            const size_t i0 = (size_t)(crow + mt * 16) * N + ccol + nt * 8;
            const size_t i1 = i0 + 8 * (size_t)N;
            if (OUT == 1) {
                uint32_t h, l;
                split2(acc[mt][nt][0] * scale, acc[mt][nt][1] * scale, h, l);
                *(uint32_t*)(Ch + i0) = h;
                *(uint32_t*)(Cl + i0) = l;
                split2(acc[mt][nt][2] * scale, acc[mt][nt][3] * scale, h, l);
                *(uint32_t*)(Ch + i1) = h;
                *(uint32_t*)(Cl + i1) = l;
            } else if (OUT == 2) {
                __half2 v0 = __floats2half2_rn(acc[mt][nt][0], acc[mt][nt][1]);
                __half2 v1 = __floats2half2_rn(acc[mt][nt][2], acc[mt][nt][3]);
                *(__half2*)(Ch + i0) = v0;
                *(__half2*)(Ch + i1) = v1;
            } else {
                *(float2*)(C + i0) = make_float2(acc[mt][nt][0], acc[mt][nt][1]);
                *(float2*)(C + i1) = make_float2(acc[mt][nt][2], acc[mt][nt][3]);
            }
        }
    }
}

// ---------------------------------------------------------------------------
// fp32 -> (hi, lo) fp16 split, elementwise
// ---------------------------------------------------------------------------
__global__ void split_kernel(const float* __restrict__ s,
                             __half* __restrict__ h,
                             __half* __restrict__ l, int n4) {
    int i = blockIdx.x * blockDim.x + threadIdx.x;
    if (i >= n4) return;
    float4 v = ((const float4*)s)[i];
    uint32_t h0, l0, h1, l1;
    split2(v.x, v.y, h0, l0);
    split2(v.z, v.w, h1, l1);
    ((uint32_t*)h)[2 * i]     = h0;
    ((uint32_t*)h)[2 * i + 1] = h1;
    ((uint32_t*)l)[2 * i]     = l0;
    ((uint32_t*)l)[2 * i + 1] = l1;
}

// ---------------------------------------------------------------------------
// Transposed single-fp16: W fp32 [K, N] -> Wt fp16 [N, K]
// ---------------------------------------------------------------------------
__global__ void splitT_kernel(const float* __restrict__ W,
                              __half* __restrict__ th, int K, int N) {
    __shared__ float t[32][33];
    const int x0 = blockIdx.x * 32;
    const int y0 = blockIdx.y * 32;
    const int tx = threadIdx.x;
#pragma unroll
    for (int j = threadIdx.y; j < 32; j += 8)
        t[j][tx] = W[(size_t)(y0 + j) * N + x0 + tx];
    __syncthreads();
#pragma unroll
    for (int j = threadIdx.y; j < 32; j += 8)
        th[(size_t)(x0 + j) * K + y0 + tx] = __float2half_rn(t[tx][j]);
}

// ---------------------------------------------------------------------------
// flash_mma: HMMA flash attention, fp16 2-pass split.
// Q smem region overlapped with K/V double buffer -> smem 36864, 2 CTAs/SM.
// grid (16 qtiles, 16 heads, 4 batch), 256 threads (8 warps x 16 q rows).
// ---------------------------------------------------------------------------
#define FPITCH_B 144                    // 72 halves
#define KTILE_B  (64 * FPITCH_B)        // 9216
#define FSTAGE_B (2 * KTILE_B)          // K + V = 18432
#define SM_FLASH (2 * FSTAGE_B)         // 36864 (also == Qh+Ql staging size)
#define NKTILES  (SEQ / 64)             // 32

__global__ __launch_bounds__(256, 2)
void flash_mma(const __half* __restrict__ qh,
               const __half* __restrict__ ql,
               const __half* __restrict__ kv,
               __half* __restrict__ oh,
               __half* __restrict__ ol) {
    extern __shared__ char smem[];
    const uint32_t sb = smem_u32(smem);
    const int tid  = threadIdx.x;
    const int wid  = tid >> 5;
    const int lane = tid & 31;
    const int b = blockIdx.z;
    const int h = blockIdx.y;
    const int qbase = blockIdx.x * 128;
    const size_t browq = (size_t)(b * SEQ + qbase);
    const size_t brow  = (size_t)(b * SEQ);

    // ---- stage Q (hi+lo) into the (future) KV buffer area
    const uint32_t qh_s = sb;
    const uint32_t ql_s = sb + 128 * FPITCH_B;   // 18432
#pragma unroll
    for (int t = tid; t < 1024; t += 256) {
        const int r = t >> 3, c = t & 7;
        const size_t g = (browq + r) * DMODEL + h * DK + c * 8;
        CP_ASYNC16(qh_s + r * FPITCH_B + c * 16, qh + g);
        CP_ASYNC16(ql_s + r * FPITCH_B + c * 16, ql + g);
    }
    CP_COMMIT();
    CP_WAIT_ALL();
    __syncthreads();

    // ---- hoist Q fragments to registers
    uint32_t qa_h[4][4], qa_l[4][4];
    {
        const uint32_t a_row = wid * 16 + (lane & 15);
        const uint32_t a_kof = (lane >> 4) * 8;
#pragma unroll
        for (int kc = 0; kc < 4; kc++) {
            ldmatrix_x4(qa_h[kc], qh_s + a_row * FPITCH_B + (kc * 16 + a_kof) * 2);
            ldmatrix_x4(qa_l[kc], ql_s + a_row * FPITCH_B + (kc * 16 + a_kof) * 2);
        }
    }
    __syncthreads();   // Q smem now dead; KV buffers may overwrite

    auto issue_kv = [&](int buf, int j0) {
        const uint32_t s0 = sb + buf * FSTAGE_B;
#pragma unroll
        for (int t = tid; t < 512; t += 256) {
            const int r = t >> 3, c = t & 7;
            const size_t g = (brow + j0 + r) * (2 * DMODEL) + h * DK + c * 8;
            const uint32_t o = r * FPITCH_B + c * 16;
            CP_ASYNC16(s0 + o,           kv + g);            // K
            CP_ASYNC16(s0 + KTILE_B + o, kv + g + DMODEL);   // V
        }
        CP_COMMIT();
    };

    issue_kv(0, 0);

    float O[8][4];
#pragma unroll
    for (int i = 0; i < 8; i++)
#pragma unroll
        for (int j = 0; j < 4; j++) O[i][j] = 0.f;
    float m0 = -1e30f, m1 = -1e30f, l0 = 0.f, l1 = 0.f;

    const uint32_t k_lrow = (lane & 7);
    const uint32_t k_kof  = ((lane >> 3) & 1) * 8;
    const uint32_t v_lrow = (lane & 15);

    for (int jt = 0; jt < NKTILES; jt++) {
        const int buf = jt & 1;
        if (jt + 1 < NKTILES) {
            issue_kv(buf ^ 1, (jt + 1) * 64);
            CP_WAIT_ONE();
        } else {
            CP_WAIT_ALL();
        }
        __syncthreads();

        const uint32_t s0 = sb + buf * FSTAGE_B;

        // ---- S = Q K^T (2-pass: Qh·K + Ql·K)
        float S[8][4];
#pragma unroll
        for (int i = 0; i < 8; i++)
#pragma unroll
            for (int j = 0; j < 4; j++) S[i][j] = 0.f;

#pragma unroll
        for (int kc = 0; kc < 4; kc++) {
#pragma unroll
            for (int nt = 0; nt < 8; nt++) {
                uint32_t bh[2];
                ldmatrix_x2(bh, s0 + (nt * 8 + k_lrow) * FPITCH_B
                                + (kc * 16 + k_kof) * 2);
                mma_16816(S[nt], qa_h[kc], bh);
                mma_16816(S[nt], qa_l[kc], bh);
            }
        }

        // ---- online softmax
        float tm0 = -1e30f, tm1 = -1e30f;
#pragma unroll
        for (int nt = 0; nt < 8; nt++) {
            tm0 = fmaxf(tm0, fmaxf(S[nt][0], S[nt][1]));
            tm1 = fmaxf(tm1, fmaxf(S[nt][2], S[nt][3]));
        }
        tm0 = fmaxf(tm0, __shfl_xor_sync(0xffffffffu, tm0, 1));
        tm0 = fmaxf(tm0, __shfl_xor_sync(0xffffffffu, tm0, 2));
        tm1 = fmaxf(tm1, __shfl_xor_sync(0xffffffffu, tm1, 1));
        tm1 = fmaxf(tm1, __shfl_xor_sync(0xffffffffu, tm1, 2));

        const float mn0 = fmaxf(m0, tm0);
        const float mn1 = fmaxf(m1, tm1);
        const float cr0 = __expf(m0 - mn0);
        const float cr1 = __expf(m1 - mn1);
        l0 *= cr0;
        l1 *= cr1;
#pragma unroll
        for (int nt = 0; nt < 8; nt++) {
            O[nt][0] *= cr0; O[nt][1] *= cr0;
            O[nt][2] *= cr1; O[nt][3] *= cr1;
        }
#pragma unroll
        for (int nt = 0; nt < 8; nt++) {
            S[nt][0] = __expf(S[nt][0] - mn0);
            S[nt][1] = __expf(S[nt][1] - mn0);
            S[nt][2] = __expf(S[nt][2] - mn1);
            S[nt][3] = __expf(S[nt][3] - mn1);
            l0 += S[nt][0] + S[nt][1];
            l1 += S[nt][2] + S[nt][3];
        }
        m0 = mn0; m1 = mn1;

        // ---- O += P V (2-pass: Ph·V + Pl·V; V single fp16)
#pragma unroll
        for (int kc = 0; kc < 4; kc++) {
            uint32_t ah[4], al[4];
            split2(S[2 * kc][0],     S[2 * kc][1],     ah[0], al[0]);
            split2(S[2 * kc][2],     S[2 * kc][3],     ah[1], al[1]);
            split2(S[2 * kc + 1][0], S[2 * kc + 1][1], ah[2], al[2]);
            split2(S[2 * kc + 1][2], S[2 * kc + 1][3], ah[3], al[3]);
#pragma unroll
            for (int nd = 0; nd < 8; nd++) {
                uint32_t bv[2];
                ldmatrix_x2_trans(bv, s0 + KTILE_B
                                  + (kc * 16 + v_lrow) * FPITCH_B + nd * 16);
                mma_16816(O[nd], ah, bv);
                mma_16816(O[nd], al, bv);
            }
        }
        __syncthreads();
    }

    // ---- epilogue
    l0 += __shfl_xor_sync(0xffffffffu, l0, 1);
    l0 += __shfl_xor_sync(0xffffffffu, l0, 2);
    l1 += __shfl_xor_sync(0xffffffffu, l1, 1);
    l1 += __shfl_xor_sync(0xffffffffu, l1, 2);
    const float inv0 = 1.f / l0;
    const float inv1 = 1.f / l1;

    const int r0 = qbase + wid * 16 + (lane >> 2);
    const int r1 = r0 + 8;
    const int col = h * DK + (lane & 3) * 2;
#pragma unroll
    for (int nd = 0; nd < 8; nd++) {
        const size_t i0 = (brow + r0) * DMODEL + col + nd * 8;
        const size_t i1 = (brow + r1) * DMODEL + col + nd * 8;
        uint32_t hw, lw;
        split2(O[nd][0] * inv0, O[nd][1] * inv0, hw, lw);
        *(uint32_t*)(oh + i0) = hw;
        *(uint32_t*)(ol + i0) = lw;
        split2(O[nd][2] * inv1, O[nd][3] * inv1, hw, lw);
        *(uint32_t*)(oh + i1) = hw;
        *(uint32_t*)(ol + i1) = lw;
    }
}

// ---------------------------------------------------------------------------
extern "C" void kernel_launch(void* const* d_in, const int* in_sizes, int n_in,
                              void* d_out, int out_size) {
    const float* x   = (const float*)d_in[0];
    const float* Wq  = (const float*)d_in[1];
    const float* Wkv = (const float*)d_in[2];
    const float* Wo  = (const float*)d_in[3];
    float* out = (float*)d_out;

    __half *xh, *xl, *qh, *ql, *kv, *oh, *ol, *wq, *wkv, *wo;
    cudaGetSymbolAddress((void**)&xh,  g_xh);
    cudaGetSymbolAddress((void**)&xl,  g_xl);
    cudaGetSymbolAddress((void**)&qh,  g_qh);
    cudaGetSymbolAddress((void**)&ql,  g_ql);
    cudaGetSymbolAddress((void**)&kv,  g_kv);
    cudaGetSymbolAddress((void**)&oh,  g_oh);
    cudaGetSymbolAddress((void**)&ol,  g_ol);
    cudaGetSymbolAddress((void**)&wq,  g_wq);
    cudaGetSymbolAddress((void**)&wkv, g_wkv);
    cudaGetSymbolAddress((void**)&wo,  g_wo);

    cudaFuncSetAttribute(gemm_mma<0>,
        cudaFuncAttributeMaxDynamicSharedMemorySize, SM_GEMM_TOTAL);
    cudaFuncSetAttribute(gemm_mma<1>,
        cudaFuncAttributeMaxDynamicSharedMemorySize, SM_GEMM_TOTAL);
    cudaFuncSetAttribute(gemm_mma<2>,
        cudaFuncAttributeMaxDynamicSharedMemorySize, SM_GEMM_TOTAL);
    cudaFuncSetAttribute(flash_mma,
        cudaFuncAttributeMaxDynamicSharedMemorySize, SM_FLASH);

    // 1) split input (hi/lo) + transpose weights (single fp16)
    {
        int n4 = ROWS * GK / 4;
        split_kernel<<<(n4 + 255) / 256, 256>>>(x, xh, xl, n4);
    }
    splitT_kernel<<<dim3(DMODEL / 32, GK / 32), dim3(32, 8)>>>(Wq, wq, GK, DMODEL);
    splitT_kernel<<<dim3(2 * DMODEL / 32, GK / 32), dim3(32, 8)>>>(Wkv, wkv, GK, 2 * DMODEL);
    splitT_kernel<<<dim3(DMODEL / 32, GK / 32), dim3(32, 8)>>>(Wo, wo, GK, DMODEL);

    // 2) projections: Q -> hi/lo (pre-scaled), KV -> single fp16
    gemm_mma<1><<<dim3(DMODEL / 128, ROWS / 128), 256, SM_GEMM_TOTAL>>>(
        xh, xl, wq, nullptr, qh, ql, 0.125f, DMODEL);
    gemm_mma<2><<<dim3(2 * DMODEL / 128, ROWS / 128), 256, SM_GEMM_TOTAL>>>(
        xh, xl, wkv, nullptr, kv, nullptr, 1.0f, 2 * DMODEL);

    // 3) attention on tensor cores
    flash_mma<<<dim3(SEQ / 128, NHEADS, BATCH), 256, SM_FLASH>>>(
        qh, ql, kv, oh, ol);

    // 4) output projection (fp32 epilogue)
    gemm_mma<0><<<dim3(DMODEL / 128, ROWS / 128), 256, SM_GEMM_TOTAL>>>(
        oh, ol, wo, out, nullptr, nullptr, 1.0f, DMODEL);
}

// round 7
// speedup vs baseline: 8.6347x; 1.1169x over previous
#include <cuda_runtime.h>
#include <cuda_fp16.h>
#include <cstdint>
#include <math.h>

#define BATCH  4
#define SEQ    2048
#define NHEADS 16
#define DK     64
#define DMODEL 1024
#define ROWS   (BATCH * SEQ)   // 8192
#define GK     1024

// ---------------------------------------------------------------------------
// Scratch (static device globals)
// ---------------------------------------------------------------------------
__device__ __half g_xh[ROWS * GK];
__device__ __half g_xl[ROWS * GK];
__device__ __half g_qh[ROWS * DMODEL];        // Q proj hi (pre-scaled)
__device__ __half g_ql[ROWS * DMODEL];
__device__ __half g_kv[ROWS * 2 * DMODEL];    // KV proj, single fp16
__device__ __half g_oh[ROWS * DMODEL];        // attention out hi
__device__ __half g_ol[ROWS * DMODEL];
__device__ __half g_wqkv[3 * DMODEL * GK];    // [Wq^T ; Wkv^T] rows 0..3071
__device__ __half g_wo[DMODEL * GK];

// ---------------------------------------------------------------------------
// helpers
// ---------------------------------------------------------------------------
__device__ __forceinline__ uint32_t smem_u32(const void* p) {
    uint32_t a;
    asm("{ .reg .u64 t; cvta.to.shared.u64 t, %1; cvt.u32.u64 %0, t; }"
        : "=r"(a) : "l"(p));
    return a;
}

#define CP_ASYNC16(dst, src) \
    asm volatile("cp.async.cg.shared.global [%0], [%1], 16;" \
                 :: "r"(dst), "l"(src) : "memory")
#define CP_COMMIT()   asm volatile("cp.async.commit_group;" ::: "memory")
#define CP_WAIT_ALL() asm volatile("cp.async.wait_group 0;" ::: "memory")
#define CP_WAIT_ONE() asm volatile("cp.async.wait_group 1;" ::: "memory")

__device__ __forceinline__ void ldmatrix_x4(uint32_t* r, uint32_t addr) {
    asm volatile("ldmatrix.sync.aligned.m8n8.x4.shared.b16 {%0,%1,%2,%3}, [%4];"
                 : "=r"(r[0]), "=r"(r[1]), "=r"(r[2]), "=r"(r[3]) : "r"(addr));
}
__device__ __forceinline__ void ldmatrix_x2(uint32_t* r, uint32_t addr) {
    asm volatile("ldmatrix.sync.aligned.m8n8.x2.shared.b16 {%0,%1}, [%2];"
                 : "=r"(r[0]), "=r"(r[1]) : "r"(addr));
}
__device__ __forceinline__ void ldmatrix_x2_trans(uint32_t* r, uint32_t addr) {
    asm volatile("ldmatrix.sync.aligned.m8n8.x2.trans.shared.b16 {%0,%1}, [%2];"
                 : "=r"(r[0]), "=r"(r[1]) : "r"(addr));
}
__device__ __forceinline__ void mma_16816(float* c, const uint32_t* a,
                                          const uint32_t* b) {
    asm volatile(
        "mma.sync.aligned.m16n8k16.row.col.f32.f16.f16.f32 "
        "{%0,%1,%2,%3}, {%4,%5,%6,%7}, {%8,%9}, {%0,%1,%2,%3};"
        : "+f"(c[0]), "+f"(c[1]), "+f"(c[2]), "+f"(c[3])
        : "r"(a[0]), "r"(a[1]), "r"(a[2]), "r"(a[3]), "r"(b[0]), "r"(b[1]));
}

// pack (p0, p1) into fp16x2 hi word + fp16x2 lo-residual word
__device__ __forceinline__ void split2(float p0, float p1,
                                       uint32_t& h, uint32_t& l) {
    __half2 hh = __floats2half2_rn(p0, p1);
    float2 hf = __half22float2(hh);
    __half2 ll = __floats2half2_rn(p0 - hf.x, p1 - hf.y);
    h = *(uint32_t*)&hh;
    l = *(uint32_t*)&ll;
}

__device__ __forceinline__ uint32_t pack_half2(float p0, float p1) {
    __half2 hh = __floats2half2_rn(p0, p1);
    return *(uint32_t*)&hh;
}

// ---------------------------------------------------------------------------
// split-fp16 HMMA GEMM (2-pass): C = A @ W^T
//   A [M,GK] as Ah/Al fp16 hi/lo, W transposed [N,GK] single fp16.
// OUT: 0 -> fp32 C
//      3 -> merged QKV epilogue: bx<8 writes Q (hi/lo, scaled) into Qh/Ql
//           (row stride 1024), bx>=8 writes KV single fp16 (row stride 2048).
// CTA 128x128, K staged 32, 2-stage cp.async, 8 warps (2x4). 2 CTAs/SM.
// ---------------------------------------------------------------------------
#define TPITCH_B 80
#define TILE_B   (128 * TPITCH_B)       // 10240
#define STAGE_B  (3 * TILE_B)           // Ah, Al, B = 30720
#define SM_GEMM_TOTAL (2 * STAGE_B)     // 61440
#define NKS (GK / 32)                   // 32

template <int OUT>
__global__ __launch_bounds__(256, 2)
void gemm_mma(const __half* __restrict__ Ah,
              const __half* __restrict__ Al,
              const __half* __restrict__ B,
              float* __restrict__ C,
              __half* __restrict__ Qh,
              __half* __restrict__ Ql,
              __half* __restrict__ KV,
              int N) {
    extern __shared__ char smem[];
    const uint32_t sb = smem_u32(smem);
    const int tid  = threadIdx.x;
    const int wid  = tid >> 5;
    const int lane = tid & 31;
    const int warp_m = wid >> 2;
    const int warp_n = wid & 3;
    const int bx = blockIdx.x;
    const int by = blockIdx.y;

    const __half* pAh = Ah + (size_t)(by * 128) * GK;
    const __half* pAl = Al + (size_t)(by * 128) * GK;
    const __half* pB  = B  + (size_t)(bx * 128) * GK;

    float acc[4][4][4];
#pragma unroll
    for (int i = 0; i < 4; i++)
#pragma unroll
        for (int j = 0; j < 4; j++)
#pragma unroll
            for (int v = 0; v < 4; v++) acc[i][j][v] = 0.f;

    const int r0 = (tid * 2) >> 2;
    const int c0 = (tid * 2) & 3;
    const int r1 = (tid * 2 + 1) >> 2;
    const int c1 = (tid * 2 + 1) & 3;

    auto issue_stage = [&](int buf, int k0) {
        const uint32_t s0 = sb + buf * STAGE_B;
        const size_t g0 = (size_t)r0 * GK + k0 + c0 * 8;
        const size_t g1 = (size_t)r1 * GK + k0 + c1 * 8;
        const uint32_t o0 = r0 * TPITCH_B + c0 * 16;
        const uint32_t o1 = r1 * TPITCH_B + c1 * 16;
        CP_ASYNC16(s0 + o0,              pAh + g0);
        CP_ASYNC16(s0 + o1,              pAh + g1);
        CP_ASYNC16(s0 + TILE_B + o0,     pAl + g0);
        CP_ASYNC16(s0 + TILE_B + o1,     pAl + g1);
        CP_ASYNC16(s0 + 2 * TILE_B + o0, pB + g0);
        CP_ASYNC16(s0 + 2 * TILE_B + o1, pB + g1);
        CP_COMMIT();
    };

    const uint32_t a_row = warp_m * 64 + (lane & 15);
    const uint32_t a_kof = (lane >> 4) * 8;
    const uint32_t b_row = warp_n * 32 + (lane & 7);
    const uint32_t b_kof = ((lane >> 3) & 1) * 8;

    issue_stage(0, 0);

    for (int ks = 0; ks < NKS; ks++) {
        const int buf = ks & 1;
        CP_WAIT_ALL();
        __syncthreads();
        if (ks + 1 < NKS) issue_stage(buf ^ 1, (ks + 1) * 32);

        const uint32_t s0 = sb + buf * STAGE_B;
#pragma unroll
        for (int pass = 0; pass < 2; pass++) {
            const uint32_t aoff = pass ? TILE_B : 0u;
            const uint32_t boff = 2u * TILE_B;
#pragma unroll
            for (int kk = 0; kk < 32; kk += 16) {
                uint32_t afr[4][4], bfr[4][2];
#pragma unroll
                for (int mt = 0; mt < 4; mt++)
                    ldmatrix_x4(afr[mt],
                        s0 + aoff + (a_row + mt * 16) * TPITCH_B
                           + (kk + a_kof) * 2);
#pragma unroll
                for (int nt = 0; nt < 4; nt++)
                    ldmatrix_x2(bfr[nt],
                        s0 + boff + (b_row + nt * 8) * TPITCH_B
                           + (kk + b_kof) * 2);
#pragma unroll
                for (int mt = 0; mt < 4; mt++)
#pragma unroll
                    for (int nt = 0; nt < 4; nt++)
                        mma_16816(acc[mt][nt], afr[mt], bfr[nt]);
            }
        }
    }

    __syncthreads();
    const int crow = by * 128 + warp_m * 64 + (lane >> 2);

    if (OUT == 0) {
        const int ccol = bx * 128 + warp_n * 32 + (lane & 3) * 2;
#pragma unroll
        for (int mt = 0; mt < 4; mt++)
#pragma unroll
            for (int nt = 0; nt < 4; nt++) {
                const size_t i0 = (size_t)(crow + mt * 16) * N + ccol + nt * 8;
                const size_t i1 = i0 + 8 * (size_t)N;
                *(float2*)(C + i0) = make_float2(acc[mt][nt][0], acc[mt][nt][1]);
                *(float2*)(C + i1) = make_float2(acc[mt][nt][2], acc[mt][nt][3]);
            }
    } else {
        if (bx < 8) {  // Q: hi/lo, pre-scaled by 1/sqrt(dk), row stride 1024
            const int ccol = bx * 128 + warp_n * 32 + (lane & 3) * 2;
#pragma unroll
            for (int mt = 0; mt < 4; mt++)
#pragma unroll
                for (int nt = 0; nt < 4; nt++) {
                    const size_t i0 = (size_t)(crow + mt * 16) * DMODEL + ccol + nt * 8;
                    const size_t i1 = i0 + 8 * (size_t)DMODEL;
                    uint32_t h, l;
                    split2(acc[mt][nt][0] * 0.125f, acc[mt][nt][1] * 0.125f, h, l);
                    *(uint32_t*)(Qh + i0) = h;
                    *(uint32_t*)(Ql + i0) = l;
                    split2(acc[mt][nt][2] * 0.125f, acc[mt][nt][3] * 0.125f, h, l);
                    *(uint32_t*)(Qh + i1) = h;
                    *(uint32_t*)(Ql + i1) = l;
                }
        } else {       // KV: single fp16, row stride 2048
            const int ccol = (bx - 8) * 128 + warp_n * 32 + (lane & 3) * 2;
#pragma unroll
            for (int mt = 0; mt < 4; mt++)
#pragma unroll
                for (int nt = 0; nt < 4; nt++) {
                    const size_t i0 = (size_t)(crow + mt * 16) * (2 * DMODEL) + ccol + nt * 8;
                    const size_t i1 = i0 + 8 * (size_t)(2 * DMODEL);
                    *(uint32_t*)(KV + i0) = pack_half2(acc[mt][nt][0], acc[mt][nt][1]);
                    *(uint32_t*)(KV + i1) = pack_half2(acc[mt][nt][2], acc[mt][nt][3]);
                }
        }
    }
}

// ---------------------------------------------------------------------------
// fp32 -> (hi, lo) fp16 split, elementwise
// ---------------------------------------------------------------------------
__global__ void split_kernel(const float* __restrict__ s,
                             __half* __restrict__ h,
                             __half* __restrict__ l, int n4) {
    int i = blockIdx.x * blockDim.x + threadIdx.x;
    if (i >= n4) return;
    float4 v = ((const float4*)s)[i];
    uint32_t h0, l0, h1, l1;
    split2(v.x, v.y, h0, l0);
    split2(v.z, v.w, h1, l1);
    ((uint32_t*)h)[2 * i]     = h0;
    ((uint32_t*)h)[2 * i + 1] = h1;
    ((uint32_t*)l)[2 * i]     = l0;
    ((uint32_t*)l)[2 * i + 1] = l1;
}

// ---------------------------------------------------------------------------
// Transposed single-fp16: W fp32 [K, N] -> Wt fp16 [N, K]
// ---------------------------------------------------------------------------
__global__ void splitT_kernel(const float* __restrict__ W,
                              __half* __restrict__ th, int K, int N) {
    __shared__ float t[32][33];
    const int x0 = blockIdx.x * 32;
    const int y0 = blockIdx.y * 32;
    const int tx = threadIdx.x;
#pragma unroll
    for (int j = threadIdx.y; j < 32; j += 8)
        t[j][tx] = W[(size_t)(y0 + j) * N + x0 + tx];
    __syncthreads();
#pragma unroll
    for (int j = threadIdx.y; j < 32; j += 8)
        th[(size_t)(x0 + j) * K + y0 + tx] = __float2half_rn(t[tx][j]);
}

// ---------------------------------------------------------------------------
// flash_mma: HMMA flash attention.
// QK^T: 2-pass (Qh·K + Ql·K). PV: single-pass (P fp16).
// Q smem overlapped with K/V double buffer -> smem 36864, 2 CTAs/SM.
// ---------------------------------------------------------------------------
#define FPITCH_B 144                    // 72 halves
#define KTILE_B  (64 * FPITCH_B)        // 9216
#define FSTAGE_B (2 * KTILE_B)          // K + V = 18432
#define SM_FLASH (2 * FSTAGE_B)         // 36864
#define NKTILES  (SEQ / 64)             // 32

__global__ __launch_bounds__(256, 2)
void flash_mma(const __half* __restrict__ qh,
               const __half* __restrict__ ql,
               const __half* __restrict__ kv,
               __half* __restrict__ oh,
               __half* __restrict__ ol) {
    extern __shared__ char smem[];
    const uint32_t sb = smem_u32(smem);
    const int tid  = threadIdx.x;
    const int wid  = tid >> 5;
    const int lane = tid & 31;
    const int b = blockIdx.z;
    const int h = blockIdx.y;
    const int qbase = blockIdx.x * 128;
    const size_t browq = (size_t)(b * SEQ + qbase);
    const size_t brow  = (size_t)(b * SEQ);

    // ---- stage Q (hi+lo) into the (future) KV buffer area
    const uint32_t qh_s = sb;
    const uint32_t ql_s = sb + 128 * FPITCH_B;
#pragma unroll
    for (int t = tid; t < 1024; t += 256) {
        const int r = t >> 3, c = t & 7;
        const size_t g = (browq + r) * DMODEL + h * DK + c * 8;
        CP_ASYNC16(qh_s + r * FPITCH_B + c * 16, qh + g);
        CP_ASYNC16(ql_s + r * FPITCH_B + c * 16, ql + g);
    }
    CP_COMMIT();
    CP_WAIT_ALL();
    __syncthreads();

    // ---- hoist Q fragments to registers
    uint32_t qa_h[4][4], qa_l[4][4];
    {
        const uint32_t a_row = wid * 16 + (lane & 15);
        const uint32_t a_kof = (lane >> 4) * 8;
#pragma unroll
        for (int kc = 0; kc < 4; kc++) {
            ldmatrix_x4(qa_h[kc], qh_s + a_row * FPITCH_B + (kc * 16 + a_kof) * 2);
            ldmatrix_x4(qa_l[kc], ql_s + a_row * FPITCH_B + (kc * 16 + a_kof) * 2);
        }
    }
    __syncthreads();   // Q smem now dead; KV buffers may overwrite

    auto issue_kv = [&](int buf, int j0) {
        const uint32_t s0 = sb + buf * FSTAGE_B;
#pragma unroll
        for (int t = tid; t < 512; t += 256) {
            const int r = t >> 3, c = t & 7;
            const size_t g = (brow + j0 + r) * (2 * DMODEL) + h * DK + c * 8;
            const uint32_t o = r * FPITCH_B + c * 16;
            CP_ASYNC16(s0 + o,           kv + g);            // K
            CP_ASYNC16(s0 + KTILE_B + o, kv + g + DMODEL);   // V
        }
        CP_COMMIT();
    };

    issue_kv(0, 0);

    float O[8][4];
#pragma unroll
    for (int i = 0; i < 8; i++)
#pragma unroll
        for (int j = 0; j < 4; j++) O[i][j] = 0.f;
    float m0 = -1e30f, m1 = -1e30f, l0 = 0.f, l1 = 0.f;

    const uint32_t k_lrow = (lane & 7);
    const uint32_t k_kof  = ((lane >> 3) & 1) * 8;
    const uint32_t v_lrow = (lane & 15);

    for (int jt = 0; jt < NKTILES; jt++) {
        const int buf = jt & 1;
        if (jt + 1 < NKTILES) {
            issue_kv(buf ^ 1, (jt + 1) * 64);
            CP_WAIT_ONE();
        } else {
            CP_WAIT_ALL();
        }
        __syncthreads();

        const uint32_t s0 = sb + buf * FSTAGE_B;

        // ---- S = Q K^T (2-pass: Qh·K + Ql·K)
        float S[8][4];
#pragma unroll
        for (int i = 0; i < 8; i++)
#pragma unroll
            for (int j = 0; j < 4; j++) S[i][j] = 0.f;

#pragma unroll
        for (int kc = 0; kc < 4; kc++) {
#pragma unroll
            for (int nt = 0; nt < 8; nt++) {
                uint32_t bh[2];
                ldmatrix_x2(bh, s0 + (nt * 8 + k_lrow) * FPITCH_B
                                + (kc * 16 + k_kof) * 2);
                mma_16816(S[nt], qa_h[kc], bh);
                mma_16816(S[nt], qa_l[kc], bh);
            }
        }

        // ---- online softmax
        float tm0 = -1e30f, tm1 = -1e30f;
#pragma unroll
        for (int nt = 0; nt < 8; nt++) {
            tm0 = fmaxf(tm0, fmaxf(S[nt][0], S[nt][1]));
            tm1 = fmaxf(tm1, fmaxf(S[nt][2], S[nt][3]));
        }
        tm0 = fmaxf(tm0, __shfl_xor_sync(0xffffffffu, tm0, 1));
        tm0 = fmaxf(tm0, __shfl_xor_sync(0xffffffffu, tm0, 2));
        tm1 = fmaxf(tm1, __shfl_xor_sync(0xffffffffu, tm1, 1));
        tm1 = fmaxf(tm1, __shfl_xor_sync(0xffffffffu, tm1, 2));

        const float mn0 = fmaxf(m0, tm0);
        const float mn1 = fmaxf(m1, tm1);
        const float cr0 = __expf(m0 - mn0);
        const float cr1 = __expf(m1 - mn1);
        l0 *= cr0;
        l1 *= cr1;
#pragma unroll
        for (int nt = 0; nt < 8; nt++) {
            O[nt][0] *= cr0; O[nt][1] *= cr0;
            O[nt][2] *= cr1; O[nt][3] *= cr1;
        }
#pragma unroll
        for (int nt = 0; nt < 8; nt++) {
            S[nt][0] = __expf(S[nt][0] - mn0);
            S[nt][1] = __expf(S[nt][1] - mn0);
            S[nt][2] = __expf(S[nt][2] - mn1);
            S[nt][3] = __expf(S[nt][3] - mn1);
            l0 += S[nt][0] + S[nt][1];
            l1 += S[nt][2] + S[nt][3];
        }
        m0 = mn0; m1 = mn1;

        // ---- O += P V (single-pass: P fp16, V fp16)
#pragma unroll
        for (int kc = 0; kc < 4; kc++) {
            uint32_t ah[4];
            ah[0] = pack_half2(S[2 * kc][0],     S[2 * kc][1]);
            ah[1] = pack_half2(S[2 * kc][2],     S[2 * kc][3]);
            ah[2] = pack_half2(S[2 * kc + 1][0], S[2 * kc + 1][1]);
            ah[3] = pack_half2(S[2 * kc + 1][2], S[2 * kc + 1][3]);
#pragma unroll
            for (int nd = 0; nd < 8; nd++) {
                uint32_t bv[2];
                ldmatrix_x2_trans(bv, s0 + KTILE_B
                                  + (kc * 16 + v_lrow) * FPITCH_B + nd * 16);
                mma_16816(O[nd], ah, bv);
            }
        }
        __syncthreads();
    }

    // ---- epilogue
    l0 += __shfl_xor_sync(0xffffffffu, l0, 1);
    l0 += __shfl_xor_sync(0xffffffffu, l0, 2);
    l1 += __shfl_xor_sync(0xffffffffu, l1, 1);
    l1 += __shfl_xor_sync(0xffffffffu, l1, 2);
    const float inv0 = 1.f / l0;
    const float inv1 = 1.f / l1;

    const int r0 = qbase + wid * 16 + (lane >> 2);
    const int r1 = r0 + 8;
    const int col = h * DK + (lane & 3) * 2;
#pragma unroll
    for (int nd = 0; nd < 8; nd++) {
        const size_t i0 = (brow + r0) * DMODEL + col + nd * 8;
        const size_t i1 = (brow + r1) * DMODEL + col + nd * 8;
        uint32_t hw, lw;
        split2(O[nd][0] * inv0, O[nd][1] * inv0, hw, lw);
        *(uint32_t*)(oh + i0) = hw;
        *(uint32_t*)(ol + i0) = lw;
        split2(O[nd][2] * inv1, O[nd][3] * inv1, hw, lw);
        *(uint32_t*)(oh + i1) = hw;
        *(uint32_t*)(ol + i1) = lw;
    }
}

// ---------------------------------------------------------------------------
extern "C" void kernel_launch(void* const* d_in, const int* in_sizes, int n_in,
                              void* d_out, int out_size) {
    const float* x   = (const float*)d_in[0];
    const float* Wq  = (const float*)d_in[1];
    const float* Wkv = (const float*)d_in[2];
    const float* Wo  = (const float*)d_in[3];
    float* out = (float*)d_out;

    __half *xh, *xl, *qh, *ql, *kv, *oh, *ol, *wqkv, *wo;
    cudaGetSymbolAddress((void**)&xh,   g_xh);
    cudaGetSymbolAddress((void**)&xl,   g_xl);
    cudaGetSymbolAddress((void**)&qh,   g_qh);
    cudaGetSymbolAddress((void**)&ql,   g_ql);
    cudaGetSymbolAddress((void**)&kv,   g_kv);
    cudaGetSymbolAddress((void**)&oh,   g_oh);
    cudaGetSymbolAddress((void**)&ol,   g_ol);
    cudaGetSymbolAddress((void**)&wqkv, g_wqkv);
    cudaGetSymbolAddress((void**)&wo,   g_wo);

    cudaFuncSetAttribute(gemm_mma<0>,
        cudaFuncAttributeMaxDynamicSharedMemorySize, SM_GEMM_TOTAL);
    cudaFuncSetAttribute(gemm_mma<3>,
        cudaFuncAttributeMaxDynamicSharedMemorySize, SM_GEMM_TOTAL);
    cudaFuncSetAttribute(flash_mma,
        cudaFuncAttributeMaxDynamicSharedMemorySize, SM_FLASH);

    // 1) split input (hi/lo) + transpose weights into combined buffer
    {
        int n4 = ROWS * GK / 4;
        split_kernel<<<(n4 + 255) / 256, 256>>>(x, xh, xl, n4);
    }
    splitT_kernel<<<dim3(DMODEL / 32, GK / 32), dim3(32, 8)>>>(Wq, wqkv, GK, DMODEL);
    splitT_kernel<<<dim3(2 * DMODEL / 32, GK / 32), dim3(32, 8)>>>(
        Wkv, wqkv + (size_t)DMODEL * GK, GK, 2 * DMODEL);
    splitT_kernel<<<dim3(DMODEL / 32, GK / 32), dim3(32, 8)>>>(Wo, wo, GK, DMODEL);

    // 2) merged QKV projection (one launch)
    gemm_mma<3><<<dim3(3 * DMODEL / 128, ROWS / 128), 256, SM_GEMM_TOTAL>>>(
        xh, xl, wqkv, nullptr, qh, ql, kv, 3 * DMODEL);

    // 3) attention on tensor cores
    flash_mma<<<dim3(SEQ / 128, NHEADS, BATCH), 256, SM_FLASH>>>(
        qh, ql, kv, oh, ol);

    // 4) output projection (fp32 epilogue)
    gemm_mma<0><<<dim3(DMODEL / 128, ROWS / 128), 256, SM_GEMM_TOTAL>>>(
        oh, ol, wo, out, nullptr, nullptr, nullptr, DMODEL);
}

// round 8
// speedup vs baseline: 9.5341x; 1.1042x over previous
#include <cuda_runtime.h>
#include <cuda_fp16.h>
#include <cstdint>
#include <math.h>

#define BATCH  4
#define SEQ    2048
#define NHEADS 16
#define DK     64
#define DMODEL 1024
#define ROWS   (BATCH * SEQ)   // 8192
#define GK     1024

// ---------------------------------------------------------------------------
// Scratch (static device globals)
// ---------------------------------------------------------------------------
__device__ __half g_xh[ROWS * GK];
__device__ __half g_xl[ROWS * GK];
__device__ __half g_q[ROWS * DMODEL];         // Q proj, single fp16 (pre-scaled)
__device__ __half g_kv[ROWS * 2 * DMODEL];    // KV proj, single fp16
__device__ __half g_oh[ROWS * DMODEL];        // attention out hi
__device__ __half g_ol[ROWS * DMODEL];        // attention out lo
__device__ __half g_wqkv[3 * DMODEL * GK];    // [Wq^T ; Wkv^T]
__device__ __half g_wo[DMODEL * GK];

// ---------------------------------------------------------------------------
// helpers
// ---------------------------------------------------------------------------
__device__ __forceinline__ uint32_t smem_u32(const void* p) {
    uint32_t a;
    asm("{ .reg .u64 t; cvta.to.shared.u64 t, %1; cvt.u32.u64 %0, t; }"
        : "=r"(a) : "l"(p));
    return a;
}

#define CP_ASYNC16(dst, src) \
    asm volatile("cp.async.cg.shared.global [%0], [%1], 16;" \
                 :: "r"(dst), "l"(src) : "memory")
#define CP_COMMIT()   asm volatile("cp.async.commit_group;" ::: "memory")
#define CP_WAIT_ALL() asm volatile("cp.async.wait_group 0;" ::: "memory")
#define CP_WAIT_ONE() asm volatile("cp.async.wait_group 1;" ::: "memory")

__device__ __forceinline__ void ldmatrix_x4(uint32_t* r, uint32_t addr) {
    asm volatile("ldmatrix.sync.aligned.m8n8.x4.shared.b16 {%0,%1,%2,%3}, [%4];"
                 : "=r"(r[0]), "=r"(r[1]), "=r"(r[2]), "=r"(r[3]) : "r"(addr));
}
__device__ __forceinline__ void ldmatrix_x2(uint32_t* r, uint32_t addr) {
    asm volatile("ldmatrix.sync.aligned.m8n8.x2.shared.b16 {%0,%1}, [%2];"
                 : "=r"(r[0]), "=r"(r[1]) : "r"(addr));
}
__device__ __forceinline__ void ldmatrix_x2_trans(uint32_t* r, uint32_t addr) {
    asm volatile("ldmatrix.sync.aligned.m8n8.x2.trans.shared.b16 {%0,%1}, [%2];"
                 : "=r"(r[0]), "=r"(r[1]) : "r"(addr));
}
__device__ __forceinline__ void mma_16816(float* c, const uint32_t* a,
                                          const uint32_t* b) {
    asm volatile(
        "mma.sync.aligned.m16n8k16.row.col.f32.f16.f16.f32 "
        "{%0,%1,%2,%3}, {%4,%5,%6,%7}, {%8,%9}, {%0,%1,%2,%3};"
        : "+f"(c[0]), "+f"(c[1]), "+f"(c[2]), "+f"(c[3])
        : "r"(a[0]), "r"(a[1]), "r"(a[2]), "r"(a[3]), "r"(b[0]), "r"(b[1]));
}

// pack (p0, p1) into fp16x2 hi word + fp16x2 lo-residual word
__device__ __forceinline__ void split2(float p0, float p1,
                                       uint32_t& h, uint32_t& l) {
    __half2 hh = __floats2half2_rn(p0, p1);
    float2 hf = __half22float2(hh);
    __half2 ll = __floats2half2_rn(p0 - hf.x, p1 - hf.y);
    h = *(uint32_t*)&hh;
    l = *(uint32_t*)&ll;
}

__device__ __forceinline__ uint32_t pack_half2(float p0, float p1) {
    __half2 hh = __floats2half2_rn(p0, p1);
    return *(uint32_t*)&hh;
}

// ---------------------------------------------------------------------------
// split-fp16 HMMA GEMM (2-pass on A): C = A @ W^T
//   A [M,GK] as Ah/Al fp16 hi/lo, W transposed [N,GK] single fp16.
// OUT: 0 -> fp32 C
//      3 -> merged QKV epilogue: bx<8 writes Q single fp16 scaled (stride 1024),
//           bx>=8 writes KV single fp16 (stride 2048).
// CTA 128x128, K staged 32, 2-stage cp.async, 8 warps (2x4). 2 CTAs/SM.
// ---------------------------------------------------------------------------
#define TPITCH_B 80
#define TILE_B   (128 * TPITCH_B)       // 10240
#define STAGE_B  (3 * TILE_B)           // Ah, Al, B = 30720
#define SM_GEMM_TOTAL (2 * STAGE_B)     // 61440
#define NKS (GK / 32)                   // 32

template <int OUT>
__global__ __launch_bounds__(256, 2)
void gemm_mma(const __half* __restrict__ Ah,
              const __half* __restrict__ Al,
              const __half* __restrict__ B,
              float* __restrict__ C,
              __half* __restrict__ Q,
              __half* __restrict__ KV,
              int N) {
    extern __shared__ char smem[];
    const uint32_t sb = smem_u32(smem);
    const int tid  = threadIdx.x;
    const int wid  = tid >> 5;
    const int lane = tid & 31;
    const int warp_m = wid >> 2;
    const int warp_n = wid & 3;
    const int bx = blockIdx.x;
    const int by = blockIdx.y;

    const __half* pAh = Ah + (size_t)(by * 128) * GK;
    const __half* pAl = Al + (size_t)(by * 128) * GK;
    const __half* pB  = B  + (size_t)(bx * 128) * GK;

    float acc[4][4][4];
#pragma unroll
    for (int i = 0; i < 4; i++)
#pragma unroll
        for (int j = 0; j < 4; j++)
#pragma unroll
            for (int v = 0; v < 4; v++) acc[i][j][v] = 0.f;

    const int r0 = (tid * 2) >> 2;
    const int c0 = (tid * 2) & 3;
    const int r1 = (tid * 2 + 1) >> 2;
    const int c1 = (tid * 2 + 1) & 3;

    auto issue_stage = [&](int buf, int k0) {
        const uint32_t s0 = sb + buf * STAGE_B;
        const size_t g0 = (size_t)r0 * GK + k0 + c0 * 8;
        const size_t g1 = (size_t)r1 * GK + k0 + c1 * 8;
        const uint32_t o0 = r0 * TPITCH_B + c0 * 16;
        const uint32_t o1 = r1 * TPITCH_B + c1 * 16;
        CP_ASYNC16(s0 + o0,              pAh + g0);
        CP_ASYNC16(s0 + o1,              pAh + g1);
        CP_ASYNC16(s0 + TILE_B + o0,     pAl + g0);
        CP_ASYNC16(s0 + TILE_B + o1,     pAl + g1);
        CP_ASYNC16(s0 + 2 * TILE_B + o0, pB + g0);
        CP_ASYNC16(s0 + 2 * TILE_B + o1, pB + g1);
        CP_COMMIT();
    };

    const uint32_t a_row = warp_m * 64 + (lane & 15);
    const uint32_t a_kof = (lane >> 4) * 8;
    const uint32_t b_row = warp_n * 32 + (lane & 7);
    const uint32_t b_kof = ((lane >> 3) & 1) * 8;

    issue_stage(0, 0);

    for (int ks = 0; ks < NKS; ks++) {
        const int buf = ks & 1;
        CP_WAIT_ALL();
        __syncthreads();
        if (ks + 1 < NKS) issue_stage(buf ^ 1, (ks + 1) * 32);

        const uint32_t s0 = sb + buf * STAGE_B;
#pragma unroll
        for (int pass = 0; pass < 2; pass++) {
            const uint32_t aoff = pass ? TILE_B : 0u;
            const uint32_t boff = 2u * TILE_B;
#pragma unroll
            for (int kk = 0; kk < 32; kk += 16) {
                uint32_t afr[4][4], bfr[4][2];
#pragma unroll
                for (int mt = 0; mt < 4; mt++)
                    ldmatrix_x4(afr[mt],
                        s0 + aoff + (a_row + mt * 16) * TPITCH_B
                           + (kk + a_kof) * 2);
#pragma unroll
                for (int nt = 0; nt < 4; nt++)
                    ldmatrix_x2(bfr[nt],
                        s0 + boff + (b_row + nt * 8) * TPITCH_B
                           + (kk + b_kof) * 2);
#pragma unroll
                for (int mt = 0; mt < 4; mt++)
#pragma unroll
                    for (int nt = 0; nt < 4; nt++)
                        mma_16816(acc[mt][nt], afr[mt], bfr[nt]);
            }
        }
    }

    __syncthreads();
    const int crow = by * 128 + warp_m * 64 + (lane >> 2);

    if (OUT == 0) {
        const int ccol = bx * 128 + warp_n * 32 + (lane & 3) * 2;
#pragma unroll
        for (int mt = 0; mt < 4; mt++)
#pragma unroll
            for (int nt = 0; nt < 4; nt++) {
                const size_t i0 = (size_t)(crow + mt * 16) * N + ccol + nt * 8;
                const size_t i1 = i0 + 8 * (size_t)N;
                *(float2*)(C + i0) = make_float2(acc[mt][nt][0], acc[mt][nt][1]);
                *(float2*)(C + i1) = make_float2(acc[mt][nt][2], acc[mt][nt][3]);
            }
    } else {
        if (bx < 8) {  // Q: single fp16, pre-scaled by 1/sqrt(dk), stride 1024
            const int ccol = bx * 128 + warp_n * 32 + (lane & 3) * 2;
#pragma unroll
            for (int mt = 0; mt < 4; mt++)
#pragma unroll
                for (int nt = 0; nt < 4; nt++) {
                    const size_t i0 = (size_t)(crow + mt * 16) * DMODEL + ccol + nt * 8;
                    const size_t i1 = i0 + 8 * (size_t)DMODEL;
                    *(uint32_t*)(Q + i0) =
                        pack_half2(acc[mt][nt][0] * 0.125f, acc[mt][nt][1] * 0.125f);
                    *(uint32_t*)(Q + i1) =
                        pack_half2(acc[mt][nt][2] * 0.125f, acc[mt][nt][3] * 0.125f);
                }
        } else {       // KV: single fp16, stride 2048
            const int ccol = (bx - 8) * 128 + warp_n * 32 + (lane & 3) * 2;
#pragma unroll
            for (int mt = 0; mt < 4; mt++)
#pragma unroll
                for (int nt = 0; nt < 4; nt++) {
                    const size_t i0 = (size_t)(crow + mt * 16) * (2 * DMODEL) + ccol + nt * 8;
                    const size_t i1 = i0 + 8 * (size_t)(2 * DMODEL);
                    *(uint32_t*)(KV + i0) = pack_half2(acc[mt][nt][0], acc[mt][nt][1]);
                    *(uint32_t*)(KV + i1) = pack_half2(acc[mt][nt][2], acc[mt][nt][3]);
                }
        }
    }
}

// ---------------------------------------------------------------------------
// fp32 -> (hi, lo) fp16 split, 2x float4 per thread, 16B stores
// ---------------------------------------------------------------------------
__global__ void split_kernel(const float* __restrict__ s,
                             __half* __restrict__ h,
                             __half* __restrict__ l, int n8) {
    int i = blockIdx.x * blockDim.x + threadIdx.x;
    if (i >= n8) return;
    float4 v0 = ((const float4*)s)[2 * i];
    float4 v1 = ((const float4*)s)[2 * i + 1];
    uint4 hw, lw;
    split2(v0.x, v0.y, hw.x, lw.x);
    split2(v0.z, v0.w, hw.y, lw.y);
    split2(v1.x, v1.y, hw.z, lw.z);
    split2(v1.z, v1.w, hw.w, lw.w);
    ((uint4*)h)[i] = hw;
    ((uint4*)l)[i] = lw;
}

// ---------------------------------------------------------------------------
// Transposed single-fp16: W fp32 [K, N] -> Wt fp16 [N, K]
// ---------------------------------------------------------------------------
__global__ void splitT_kernel(const float* __restrict__ W,
                              __half* __restrict__ th, int K, int N) {
    __shared__ float t[32][33];
    const int x0 = blockIdx.x * 32;
    const int y0 = blockIdx.y * 32;
    const int tx = threadIdx.x;
#pragma unroll
    for (int j = threadIdx.y; j < 32; j += 8)
        t[j][tx] = W[(size_t)(y0 + j) * N + x0 + tx];
    __syncthreads();
#pragma unroll
    for (int j = threadIdx.y; j < 32; j += 8)
        th[(size_t)(x0 + j) * K + y0 + tx] = __float2half_rn(t[tx][j]);
}

// ---------------------------------------------------------------------------
// flash_mma: HMMA flash attention.
// QK^T single-pass (Q fp16 pre-scaled); PV single-pass (P fp16).
// Output written as hi/lo fp16 (feeds Wo split-GEMM).
// Q staged through buf0 then overwritten by K/V double buffer. 2 CTAs/SM.
// ---------------------------------------------------------------------------
#define FPITCH_B 144                    // 72 halves
#define KTILE_B  (64 * FPITCH_B)        // 9216
#define FSTAGE_B (2 * KTILE_B)          // K + V = 18432
#define SM_FLASH (2 * FSTAGE_B)         // 36864
#define NKTILES  (SEQ / 64)             // 32

__global__ __launch_bounds__(256, 2)
void flash_mma(const __half* __restrict__ q,
               const __half* __restrict__ kv,
               __half* __restrict__ oh,
               __half* __restrict__ ol) {
    extern __shared__ char smem[];
    const uint32_t sb = smem_u32(smem);
    const int tid  = threadIdx.x;
    const int wid  = tid >> 5;
    const int lane = tid & 31;
    const int b = blockIdx.z;
    const int h = blockIdx.y;
    const int qbase = blockIdx.x * 128;
    const size_t browq = (size_t)(b * SEQ + qbase);
    const size_t brow  = (size_t)(b * SEQ);

    // ---- stage Q into buf0 region (16KB), then hoist to registers
#pragma unroll
    for (int t = tid; t < 1024; t += 256) {
        const int r = t >> 3, c = t & 7;
        const size_t g = (browq + r) * DMODEL + h * DK + c * 8;
        CP_ASYNC16(sb + r * FPITCH_B + c * 16, q + g);
    }
    CP_COMMIT();
    CP_WAIT_ALL();
    __syncthreads();

    uint32_t qa[4][4];
    {
        const uint32_t a_row = wid * 16 + (lane & 15);
        const uint32_t a_kof = (lane >> 4) * 8;
#pragma unroll
        for (int kc = 0; kc < 4; kc++)
            ldmatrix_x4(qa[kc], sb + a_row * FPITCH_B + (kc * 16 + a_kof) * 2);
    }
    __syncthreads();   // Q smem dead; KV buffers may overwrite

    auto issue_kv = [&](int buf, int j0) {
        const uint32_t s0 = sb + buf * FSTAGE_B;
#pragma unroll
        for (int t = tid; t < 512; t += 256) {
            const int r = t >> 3, c = t & 7;
            const size_t g = (brow + j0 + r) * (2 * DMODEL) + h * DK + c * 8;
            const uint32_t o = r * FPITCH_B + c * 16;
            CP_ASYNC16(s0 + o,           kv + g);            // K
            CP_ASYNC16(s0 + KTILE_B + o, kv + g + DMODEL);   // V
        }
        CP_COMMIT();
    };

    issue_kv(0, 0);

    float O[8][4];
#pragma unroll
    for (int i = 0; i < 8; i++)
#pragma unroll
        for (int j = 0; j < 4; j++) O[i][j] = 0.f;
    float m0 = -1e30f, m1 = -1e30f, l0 = 0.f, l1 = 0.f;

    const uint32_t k_lrow = (lane & 7);
    const uint32_t k_kof  = ((lane >> 3) & 1) * 8;
    const uint32_t v_lrow = (lane & 15);

    for (int jt = 0; jt < NKTILES; jt++) {
        const int buf = jt & 1;
        if (jt + 1 < NKTILES) {
            issue_kv(buf ^ 1, (jt + 1) * 64);
            CP_WAIT_ONE();
        } else {
            CP_WAIT_ALL();
        }
        __syncthreads();

        const uint32_t s0 = sb + buf * FSTAGE_B;

        // ---- S = Q K^T (single-pass)
        float S[8][4];
#pragma unroll
        for (int i = 0; i < 8; i++)
#pragma unroll
            for (int j = 0; j < 4; j++) S[i][j] = 0.f;

#pragma unroll
        for (int kc = 0; kc < 4; kc++) {
#pragma unroll
            for (int nt = 0; nt < 8; nt++) {
                uint32_t bh[2];
                ldmatrix_x2(bh, s0 + (nt * 8 + k_lrow) * FPITCH_B
                                + (kc * 16 + k_kof) * 2);
                mma_16816(S[nt], qa[kc], bh);
            }
        }

        // ---- online softmax
        float tm0 = -1e30f, tm1 = -1e30f;
#pragma unroll
        for (int nt = 0; nt < 8; nt++) {
            tm0 = fmaxf(tm0, fmaxf(S[nt][0], S[nt][1]));
            tm1 = fmaxf(tm1, fmaxf(S[nt][2], S[nt][3]));
        }
        tm0 = fmaxf(tm0, __shfl_xor_sync(0xffffffffu, tm0, 1));
        tm0 = fmaxf(tm0, __shfl_xor_sync(0xffffffffu, tm0, 2));
        tm1 = fmaxf(tm1, __shfl_xor_sync(0xffffffffu, tm1, 1));
        tm1 = fmaxf(tm1, __shfl_xor_sync(0xffffffffu, tm1, 2));

        const float mn0 = fmaxf(m0, tm0);
        const float mn1 = fmaxf(m1, tm1);
        const float cr0 = __expf(m0 - mn0);
        const float cr1 = __expf(m1 - mn1);
        l0 *= cr0;
        l1 *= cr1;
#pragma unroll
        for (int nt = 0; nt < 8; nt++) {
            O[nt][0] *= cr0; O[nt][1] *= cr0;
            O[nt][2] *= cr1; O[nt][3] *= cr1;
        }
#pragma unroll
        for (int nt = 0; nt < 8; nt++) {
            S[nt][0] = __expf(S[nt][0] - mn0);
            S[nt][1] = __expf(S[nt][1] - mn0);
            S[nt][2] = __expf(S[nt][2] - mn1);
            S[nt][3] = __expf(S[nt][3] - mn1);
            l0 += S[nt][0] + S[nt][1];
            l1 += S[nt][2] + S[nt][3];
        }
        m0 = mn0; m1 = mn1;

        // ---- O += P V (single-pass)
#pragma unroll
        for (int kc = 0; kc < 4; kc++) {
            uint32_t ah[4];
            ah[0] = pack_half2(S[2 * kc][0],     S[2 * kc][1]);
            ah[1] = pack_half2(S[2 * kc][2],     S[2 * kc][3]);
            ah[2] = pack_half2(S[2 * kc + 1][0], S[2 * kc + 1][1]);
            ah[3] = pack_half2(S[2 * kc + 1][2], S[2 * kc + 1][3]);
#pragma unroll
            for (int nd = 0; nd < 8; nd++) {
                uint32_t bv[2];
                ldmatrix_x2_trans(bv, s0 + KTILE_B
                                  + (kc * 16 + v_lrow) * FPITCH_B + nd * 16);
                mma_16816(O[nd], ah, bv);
            }
        }
        __syncthreads();
    }

    // ---- epilogue
    l0 += __shfl_xor_sync(0xffffffffu, l0, 1);
    l0 += __shfl_xor_sync(0xffffffffu, l0, 2);
    l1 += __shfl_xor_sync(0xffffffffu, l1, 1);
    l1 += __shfl_xor_sync(0xffffffffu, l1, 2);
    const float inv0 = 1.f / l0;
    const float inv1 = 1.f / l1;

    const int r0 = qbase + wid * 16 + (lane >> 2);
    const int r1 = r0 + 8;
    const int col = h * DK + (lane & 3) * 2;
#pragma unroll
    for (int nd = 0; nd < 8; nd++) {
        const size_t i0 = (brow + r0) * DMODEL + col + nd * 8;
        const size_t i1 = (brow + r1) * DMODEL + col + nd * 8;
        uint32_t hw, lw;
        split2(O[nd][0] * inv0, O[nd][1] * inv0, hw, lw);
        *(uint32_t*)(oh + i0) = hw;
        *(uint32_t*)(ol + i0) = lw;
        split2(O[nd][2] * inv1, O[nd][3] * inv1, hw, lw);
        *(uint32_t*)(oh + i1) = hw;
        *(uint32_t*)(ol + i1) = lw;
    }
}

// ---------------------------------------------------------------------------
extern "C" void kernel_launch(void* const* d_in, const int* in_sizes, int n_in,
                              void* d_out, int out_size) {
    const float* x   = (const float*)d_in[0];
    const float* Wq  = (const float*)d_in[1];
    const float* Wkv = (const float*)d_in[2];
    const float* Wo  = (const float*)d_in[3];
    float* out = (float*)d_out;

    __half *xh, *xl, *q, *kv, *oh, *ol, *wqkv, *wo;
    cudaGetSymbolAddress((void**)&xh,   g_xh);
    cudaGetSymbolAddress((void**)&xl,   g_xl);
    cudaGetSymbolAddress((void**)&q,    g_q);
    cudaGetSymbolAddress((void**)&kv,   g_kv);
    cudaGetSymbolAddress((void**)&oh,   g_oh);
    cudaGetSymbolAddress((void**)&ol,   g_ol);
    cudaGetSymbolAddress((void**)&wqkv, g_wqkv);
    cudaGetSymbolAddress((void**)&wo,   g_wo);

    cudaFuncSetAttribute(gemm_mma<0>,
        cudaFuncAttributeMaxDynamicSharedMemorySize, SM_GEMM_TOTAL);
    cudaFuncSetAttribute(gemm_mma<3>,
        cudaFuncAttributeMaxDynamicSharedMemorySize, SM_GEMM_TOTAL);
    cudaFuncSetAttribute(flash_mma,
        cudaFuncAttributeMaxDynamicSharedMemorySize, SM_FLASH);

    // 1) split input (hi/lo) + transpose weights into combined buffer
    {
        int n8 = ROWS * GK / 8;
        split_kernel<<<(n8 + 255) / 256, 256>>>(x, xh, xl, n8);
    }
    splitT_kernel<<<dim3(DMODEL / 32, GK / 32), dim3(32, 8)>>>(Wq, wqkv, GK, DMODEL);
    splitT_kernel<<<dim3(2 * DMODEL / 32, GK / 32), dim3(32, 8)>>>(
        Wkv, wqkv + (size_t)DMODEL * GK, GK, 2 * DMODEL);
    splitT_kernel<<<dim3(DMODEL / 32, GK / 32), dim3(32, 8)>>>(Wo, wo, GK, DMODEL);

    // 2) merged QKV projection (one launch)
    gemm_mma<3><<<dim3(3 * DMODEL / 128, ROWS / 128), 256, SM_GEMM_TOTAL>>>(
        xh, xl, wqkv, nullptr, q, kv, 3 * DMODEL);

    // 3) attention on tensor cores
    flash_mma<<<dim3(SEQ / 128, NHEADS, BATCH), 256, SM_FLASH>>>(
        q, kv, oh, ol);

    // 4) output projection (fp32 epilogue)
    gemm_mma<0><<<dim3(DMODEL / 128, ROWS / 128), 256, SM_GEMM_TOTAL>>>(
        oh, ol, wo, out, nullptr, nullptr, DMODEL);
}

// round 9
// speedup vs baseline: 13.2831x; 1.3932x over previous
#include <cuda_runtime.h>
#include <cuda_fp16.h>
#include <cstdint>
#include <math.h>

#define BATCH  4
#define SEQ    2048
#define NHEADS 16
#define DK     64
#define DMODEL 1024
#define ROWS   (BATCH * SEQ)   // 8192
#define GK     1024

// Q pre-scale: (1/sqrt(64)) * log2(e)  -> softmax uses exp2
#define QSCALE 0.1803368801111204f

// ---------------------------------------------------------------------------
// Scratch (static device globals)
// ---------------------------------------------------------------------------
__device__ __half g_x[ROWS * GK];             // x, single fp16
__device__ __half g_q[ROWS * DMODEL];         // Q proj (pre-scaled by QSCALE)
__device__ __half g_kv[ROWS * 2 * DMODEL];    // KV proj
__device__ __half g_o[ROWS * DMODEL];         // attention out
__device__ __half g_wqkv[3 * DMODEL * GK];    // [Wq^T ; Wkv^T]
__device__ __half g_wo[DMODEL * GK];

// ---------------------------------------------------------------------------
// helpers
// ---------------------------------------------------------------------------
__device__ __forceinline__ uint32_t smem_u32(const void* p) {
    uint32_t a;
    asm("{ .reg .u64 t; cvta.to.shared.u64 t, %1; cvt.u32.u64 %0, t; }"
        : "=r"(a) : "l"(p));
    return a;
}

#define CP_ASYNC16(dst, src) \
    asm volatile("cp.async.cg.shared.global [%0], [%1], 16;" \
                 :: "r"(dst), "l"(src) : "memory")
#define CP_COMMIT()   asm volatile("cp.async.commit_group;" ::: "memory")
#define CP_WAIT_ALL() asm volatile("cp.async.wait_group 0;" ::: "memory")
#define CP_WAIT_ONE() asm volatile("cp.async.wait_group 1;" ::: "memory")

__device__ __forceinline__ void ldmatrix_x4(uint32_t* r, uint32_t addr) {
    asm volatile("ldmatrix.sync.aligned.m8n8.x4.shared.b16 {%0,%1,%2,%3}, [%4];"
                 : "=r"(r[0]), "=r"(r[1]), "=r"(r[2]), "=r"(r[3]) : "r"(addr));
}
__device__ __forceinline__ void ldmatrix_x2(uint32_t* r, uint32_t addr) {
    asm volatile("ldmatrix.sync.aligned.m8n8.x2.shared.b16 {%0,%1}, [%2];"
                 : "=r"(r[0]), "=r"(r[1]) : "r"(addr));
}
__device__ __forceinline__ void ldmatrix_x2_trans(uint32_t* r, uint32_t addr) {
    asm volatile("ldmatrix.sync.aligned.m8n8.x2.trans.shared.b16 {%0,%1}, [%2];"
                 : "=r"(r[0]), "=r"(r[1]) : "r"(addr));
}
__device__ __forceinline__ void mma_16816(float* c, const uint32_t* a,
                                          const uint32_t* b) {
    asm volatile(
        "mma.sync.aligned.m16n8k16.row.col.f32.f16.f16.f32 "
        "{%0,%1,%2,%3}, {%4,%5,%6,%7}, {%8,%9}, {%0,%1,%2,%3};"
        : "+f"(c[0]), "+f"(c[1]), "+f"(c[2]), "+f"(c[3])
        : "r"(a[0]), "r"(a[1]), "r"(a[2]), "r"(a[3]), "r"(b[0]), "r"(b[1]));
}

__device__ __forceinline__ uint32_t pack_half2(float p0, float p1) {
    __half2 hh = __floats2half2_rn(p0, p1);
    return *(uint32_t*)&hh;
}

// ---------------------------------------------------------------------------
// plain fp16 HMMA GEMM: C = A @ W^T
//   A [M,GK] fp16, W transposed [N,GK] fp16, fp32 accumulate.
// OUT: 0 -> fp32 C
//      3 -> merged QKV epilogue: bx<8 writes Q fp16*QSCALE (stride 1024),
//           bx>=8 writes KV fp16 (stride 2048).
// CTA 128x128, K staged 32, 2-stage cp.async, 8 warps (2x4). 2 CTAs/SM.
// ---------------------------------------------------------------------------
#define TPITCH_B 80
#define TILE_B   (128 * TPITCH_B)       // 10240
#define STAGE_B  (2 * TILE_B)           // A, B = 20480
#define SM_GEMM_TOTAL (2 * STAGE_B)     // 40960
#define NKS (GK / 32)                   // 32

template <int OUT>
__global__ __launch_bounds__(256, 2)
void gemm_mma(const __half* __restrict__ A,
              const __half* __restrict__ B,
              float* __restrict__ C,
              __half* __restrict__ Q,
              __half* __restrict__ KV,
              int N) {
    extern __shared__ char smem[];
    const uint32_t sb = smem_u32(smem);
    const int tid  = threadIdx.x;
    const int wid  = tid >> 5;
    const int lane = tid & 31;
    const int warp_m = wid >> 2;
    const int warp_n = wid & 3;
    const int bx = blockIdx.x;
    const int by = blockIdx.y;

    const __half* pA = A + (size_t)(by * 128) * GK;
    const __half* pB = B + (size_t)(bx * 128) * GK;

    float acc[4][4][4];
#pragma unroll
    for (int i = 0; i < 4; i++)
#pragma unroll
        for (int j = 0; j < 4; j++)
#pragma unroll
            for (int v = 0; v < 4; v++) acc[i][j][v] = 0.f;

    const int r0 = (tid * 2) >> 2;
    const int c0 = (tid * 2) & 3;
    const int r1 = (tid * 2 + 1) >> 2;
    const int c1 = (tid * 2 + 1) & 3;

    auto issue_stage = [&](int buf, int k0) {
        const uint32_t s0 = sb + buf * STAGE_B;
        const size_t g0 = (size_t)r0 * GK + k0 + c0 * 8;
        const size_t g1 = (size_t)r1 * GK + k0 + c1 * 8;
        const uint32_t o0 = r0 * TPITCH_B + c0 * 16;
        const uint32_t o1 = r1 * TPITCH_B + c1 * 16;
        CP_ASYNC16(s0 + o0,          pA + g0);
        CP_ASYNC16(s0 + o1,          pA + g1);
        CP_ASYNC16(s0 + TILE_B + o0, pB + g0);
        CP_ASYNC16(s0 + TILE_B + o1, pB + g1);
        CP_COMMIT();
    };

    const uint32_t a_row = warp_m * 64 + (lane & 15);
    const uint32_t a_kof = (lane >> 4) * 8;
    const uint32_t b_row = warp_n * 32 + (lane & 7);
    const uint32_t b_kof = ((lane >> 3) & 1) * 8;

    issue_stage(0, 0);

    for (int ks = 0; ks < NKS; ks++) {
        const int buf = ks & 1;
        CP_WAIT_ALL();
        __syncthreads();
        if (ks + 1 < NKS) issue_stage(buf ^ 1, (ks + 1) * 32);

        const uint32_t s0 = sb + buf * STAGE_B;
#pragma unroll
        for (int kk = 0; kk < 32; kk += 16) {
            uint32_t afr[4][4], bfr[4][2];
#pragma unroll
            for (int mt = 0; mt < 4; mt++)
                ldmatrix_x4(afr[mt],
                    s0 + (a_row + mt * 16) * TPITCH_B + (kk + a_kof) * 2);
#pragma unroll
            for (int nt = 0; nt < 4; nt++)
                ldmatrix_x2(bfr[nt],
                    s0 + TILE_B + (b_row + nt * 8) * TPITCH_B + (kk + b_kof) * 2);
#pragma unroll
            for (int mt = 0; mt < 4; mt++)
#pragma unroll
                for (int nt = 0; nt < 4; nt++)
                    mma_16816(acc[mt][nt], afr[mt], bfr[nt]);
        }
    }

    __syncthreads();
    const int crow = by * 128 + warp_m * 64 + (lane >> 2);

    if (OUT == 0) {
        const int ccol = bx * 128 + warp_n * 32 + (lane & 3) * 2;
#pragma unroll
        for (int mt = 0; mt < 4; mt++)
#pragma unroll
            for (int nt = 0; nt < 4; nt++) {
                const size_t i0 = (size_t)(crow + mt * 16) * N + ccol + nt * 8;
                const size_t i1 = i0 + 8 * (size_t)N;
                *(float2*)(C + i0) = make_float2(acc[mt][nt][0], acc[mt][nt][1]);
                *(float2*)(C + i1) = make_float2(acc[mt][nt][2], acc[mt][nt][3]);
            }
    } else {
        if (bx < 8) {  // Q: fp16, pre-scaled by QSCALE, stride 1024
            const int ccol = bx * 128 + warp_n * 32 + (lane & 3) * 2;
#pragma unroll
            for (int mt = 0; mt < 4; mt++)
#pragma unroll
                for (int nt = 0; nt < 4; nt++) {
                    const size_t i0 = (size_t)(crow + mt * 16) * DMODEL + ccol + nt * 8;
                    const size_t i1 = i0 + 8 * (size_t)DMODEL;
                    *(uint32_t*)(Q + i0) =
                        pack_half2(acc[mt][nt][0] * QSCALE, acc[mt][nt][1] * QSCALE);
                    *(uint32_t*)(Q + i1) =
                        pack_half2(acc[mt][nt][2] * QSCALE, acc[mt][nt][3] * QSCALE);
                }
        } else {       // KV: fp16, stride 2048
            const int ccol = (bx - 8) * 128 + warp_n * 32 + (lane & 3) * 2;
#pragma unroll
            for (int mt = 0; mt < 4; mt++)
#pragma unroll
                for (int nt = 0; nt < 4; nt++) {
                    const size_t i0 = (size_t)(crow + mt * 16) * (2 * DMODEL) + ccol + nt * 8;
                    const size_t i1 = i0 + 8 * (size_t)(2 * DMODEL);
                    *(uint32_t*)(KV + i0) = pack_half2(acc[mt][nt][0], acc[mt][nt][1]);
                    *(uint32_t*)(KV + i1) = pack_half2(acc[mt][nt][2], acc[mt][nt][3]);
                }
        }
    }
}

// ---------------------------------------------------------------------------
// fp32 -> fp16 convert, 8 elems per thread
// ---------------------------------------------------------------------------
__global__ void cvt_kernel(const float* __restrict__ s,
                           __half* __restrict__ d, int n8) {
    int i = blockIdx.x * blockDim.x + threadIdx.x;
    if (i >= n8) return;
    float4 v0 = ((const float4*)s)[2 * i];
    float4 v1 = ((const float4*)s)[2 * i + 1];
    uint4 w;
    w.x = pack_half2(v0.x, v0.y);
    w.y = pack_half2(v0.z, v0.w);
    w.z = pack_half2(v1.x, v1.y);
    w.w = pack_half2(v1.z, v1.w);
    ((uint4*)d)[i] = w;
}

// ---------------------------------------------------------------------------
// Transposed fp16: W fp32 [K, N] -> Wt fp16 [N, K]
// ---------------------------------------------------------------------------
__global__ void splitT_kernel(const float* __restrict__ W,
                              __half* __restrict__ th, int K, int N) {
    __shared__ float t[32][33];
    const int x0 = blockIdx.x * 32;
    const int y0 = blockIdx.y * 32;
    const int tx = threadIdx.x;
#pragma unroll
    for (int j = threadIdx.y; j < 32; j += 8)
        t[j][tx] = W[(size_t)(y0 + j) * N + x0 + tx];
    __syncthreads();
#pragma unroll
    for (int j = threadIdx.y; j < 32; j += 8)
        th[(size_t)(x0 + j) * K + y0 + tx] = __float2half_rn(t[tx][j]);
}

// ---------------------------------------------------------------------------
// flash_mma: HMMA flash attention, all operands fp16, fp32 accum.
// Scores arrive in log2 domain (Q pre-scaled by log2e/8) -> exp2f softmax.
// Output single fp16. Q staged through buf0 then overwritten by K/V
// double buffer -> smem 36864, 2 CTAs/SM.
// ---------------------------------------------------------------------------
#define FPITCH_B 144                    // 72 halves
#define KTILE_B  (64 * FPITCH_B)        // 9216
#define FSTAGE_B (2 * KTILE_B)          // K + V = 18432
#define SM_FLASH (2 * FSTAGE_B)         // 36864
#define NKTILES  (SEQ / 64)             // 32

__global__ __launch_bounds__(256, 2)
void flash_mma(const __half* __restrict__ q,
               const __half* __restrict__ kv,
               __half* __restrict__ o) {
    extern __shared__ char smem[];
    const uint32_t sb = smem_u32(smem);
    const int tid  = threadIdx.x;
    const int wid  = tid >> 5;
    const int lane = tid & 31;
    const int b = blockIdx.z;
    const int h = blockIdx.y;
    const int qbase = blockIdx.x * 128;
    const size_t browq = (size_t)(b * SEQ + qbase);
    const size_t brow  = (size_t)(b * SEQ);

    // ---- stage Q into buf0 region, then hoist to registers
#pragma unroll
    for (int t = tid; t < 1024; t += 256) {
        const int r = t >> 3, c = t & 7;
        const size_t g = (browq + r) * DMODEL + h * DK + c * 8;
        CP_ASYNC16(sb + r * FPITCH_B + c * 16, q + g);
    }
    CP_COMMIT();
    CP_WAIT_ALL();
    __syncthreads();

    uint32_t qa[4][4];
    {
        const uint32_t a_row = wid * 16 + (lane & 15);
        const uint32_t a_kof = (lane >> 4) * 8;
#pragma unroll
        for (int kc = 0; kc < 4; kc++)
            ldmatrix_x4(qa[kc], sb + a_row * FPITCH_B + (kc * 16 + a_kof) * 2);
    }
    __syncthreads();   // Q smem dead; KV buffers may overwrite

    auto issue_kv = [&](int buf, int j0) {
        const uint32_t s0 = sb + buf * FSTAGE_B;
#pragma unroll
        for (int t = tid; t < 512; t += 256) {
            const int r = t >> 3, c = t & 7;
            const size_t g = (brow + j0 + r) * (2 * DMODEL) + h * DK + c * 8;
            const uint32_t off = r * FPITCH_B + c * 16;
            CP_ASYNC16(s0 + off,           kv + g);            // K
            CP_ASYNC16(s0 + KTILE_B + off, kv + g + DMODEL);   // V
        }
        CP_COMMIT();
    };

    issue_kv(0, 0);

    float O[8][4];
#pragma unroll
    for (int i = 0; i < 8; i++)
#pragma unroll
        for (int j = 0; j < 4; j++) O[i][j] = 0.f;
    float m0 = -1e30f, m1 = -1e30f, l0 = 0.f, l1 = 0.f;

    const uint32_t k_lrow = (lane & 7);
    const uint32_t k_kof  = ((lane >> 3) & 1) * 8;
    const uint32_t v_lrow = (lane & 15);

    for (int jt = 0; jt < NKTILES; jt++) {
        const int buf = jt & 1;
        if (jt + 1 < NKTILES) {
            issue_kv(buf ^ 1, (jt + 1) * 64);
            CP_WAIT_ONE();
        } else {
            CP_WAIT_ALL();
        }
        __syncthreads();

        const uint32_t s0 = sb + buf * FSTAGE_B;

        // ---- S = Q K^T (log2 domain)
        float S[8][4];
#pragma unroll
        for (int i = 0; i < 8; i++)
#pragma unroll
            for (int j = 0; j < 4; j++) S[i][j] = 0.f;

#pragma unroll
        for (int kc = 0; kc < 4; kc++) {
#pragma unroll
            for (int nt = 0; nt < 8; nt++) {
                uint32_t bh[2];
                ldmatrix_x2(bh, s0 + (nt * 8 + k_lrow) * FPITCH_B
                                + (kc * 16 + k_kof) * 2);
                mma_16816(S[nt], qa[kc], bh);
            }
        }

        // ---- online softmax (base-2)
        float tm0 = -1e30f, tm1 = -1e30f;
#pragma unroll
        for (int nt = 0; nt < 8; nt++) {
            tm0 = fmaxf(tm0, fmaxf(S[nt][0], S[nt][1]));
            tm1 = fmaxf(tm1, fmaxf(S[nt][2], S[nt][3]));
        }
        tm0 = fmaxf(tm0, __shfl_xor_sync(0xffffffffu, tm0, 1));
        tm0 = fmaxf(tm0, __shfl_xor_sync(0xffffffffu, tm0, 2));
        tm1 = fmaxf(tm1, __shfl_xor_sync(0xffffffffu, tm1, 1));
        tm1 = fmaxf(tm1, __shfl_xor_sync(0xffffffffu, tm1, 2));

        const float mn0 = fmaxf(m0, tm0);
        const float mn1 = fmaxf(m1, tm1);
        const float cr0 = exp2f(m0 - mn0);
        const float cr1 = exp2f(m1 - mn1);
        l0 *= cr0;
        l1 *= cr1;
#pragma unroll
        for (int nt = 0; nt < 8; nt++) {
            O[nt][0] *= cr0; O[nt][1] *= cr0;
            O[nt][2] *= cr1; O[nt][3] *= cr1;
        }
#pragma unroll
        for (int nt = 0; nt < 8; nt++) {
            S[nt][0] = exp2f(S[nt][0] - mn0);
            S[nt][1] = exp2f(S[nt][1] - mn0);
            S[nt][2] = exp2f(S[nt][2] - mn1);
            S[nt][3] = exp2f(S[nt][3] - mn1);
            l0 += S[nt][0] + S[nt][1];
            l1 += S[nt][2] + S[nt][3];
        }
        m0 = mn0; m1 = mn1;

        // ---- O += P V
#pragma unroll
        for (int kc = 0; kc < 4; kc++) {
            uint32_t ah[4];
            ah[0] = pack_half2(S[2 * kc][0],     S[2 * kc][1]);
            ah[1] = pack_half2(S[2 * kc][2],     S[2 * kc][3]);
            ah[2] = pack_half2(S[2 * kc + 1][0], S[2 * kc + 1][1]);
            ah[3] = pack_half2(S[2 * kc + 1][2], S[2 * kc + 1][3]);
#pragma unroll
            for (int nd = 0; nd < 8; nd++) {
                uint32_t bv[2];
                ldmatrix_x2_trans(bv, s0 + KTILE_B
                                  + (kc * 16 + v_lrow) * FPITCH_B + nd * 16);
                mma_16816(O[nd], ah, bv);
            }
        }
        __syncthreads();
    }

    // ---- epilogue (single fp16 output)
    l0 += __shfl_xor_sync(0xffffffffu, l0, 1);
    l0 += __shfl_xor_sync(0xffffffffu, l0, 2);
    l1 += __shfl_xor_sync(0xffffffffu, l1, 1);
    l1 += __shfl_xor_sync(0xffffffffu, l1, 2);
    const float inv0 = 1.f / l0;
    const float inv1 = 1.f / l1;

    const int r0 = qbase + wid * 16 + (lane >> 2);
    const int r1 = r0 + 8;
    const int col = h * DK + (lane & 3) * 2;
#pragma unroll
    for (int nd = 0; nd < 8; nd++) {
        const size_t i0 = (brow + r0) * DMODEL + col + nd * 8;
        const size_t i1 = (brow + r1) * DMODEL + col + nd * 8;
        *(uint32_t*)(o + i0) = pack_half2(O[nd][0] * inv0, O[nd][1] * inv0);
        *(uint32_t*)(o + i1) = pack_half2(O[nd][2] * inv1, O[nd][3] * inv1);
    }
}

// ---------------------------------------------------------------------------
extern "C" void kernel_launch(void* const* d_in, const int* in_sizes, int n_in,
                              void* d_out, int out_size) {
    const float* x   = (const float*)d_in[0];
    const float* Wq  = (const float*)d_in[1];
    const float* Wkv = (const float*)d_in[2];
    const float* Wo  = (const float*)d_in[3];
    float* out = (float*)d_out;

    __half *xf, *q, *kv, *o, *wqkv, *wo;
    cudaGetSymbolAddress((void**)&xf,   g_x);
    cudaGetSymbolAddress((void**)&q,    g_q);
    cudaGetSymbolAddress((void**)&kv,   g_kv);
    cudaGetSymbolAddress((void**)&o,    g_o);
    cudaGetSymbolAddress((void**)&wqkv, g_wqkv);
    cudaGetSymbolAddress((void**)&wo,   g_wo);

    cudaFuncSetAttribute(gemm_mma<0>,
        cudaFuncAttributeMaxDynamicSharedMemorySize, SM_GEMM_TOTAL);
    cudaFuncSetAttribute(gemm_mma<3>,
        cudaFuncAttributeMaxDynamicSharedMemorySize, SM_GEMM_TOTAL);
    cudaFuncSetAttribute(flash_mma,
        cudaFuncAttributeMaxDynamicSharedMemorySize, SM_FLASH);

    // 1) convert input + transpose weights into combined buffer
    {
        int n8 = ROWS * GK / 8;
        cvt_kernel<<<(n8 + 255) / 256, 256>>>(x, xf, n8);
    }
    splitT_kernel<<<dim3(DMODEL / 32, GK / 32), dim3(32, 8)>>>(Wq, wqkv, GK, DMODEL);
    splitT_kernel<<<dim3(2 * DMODEL / 32, GK / 32), dim3(32, 8)>>>(
        Wkv, wqkv + (size_t)DMODEL * GK, GK, 2 * DMODEL);
    splitT_kernel<<<dim3(DMODEL / 32, GK / 32), dim3(32, 8)>>>(Wo, wo, GK, DMODEL);

    // 2) merged QKV projection (one launch)
    gemm_mma<3><<<dim3(3 * DMODEL / 128, ROWS / 128), 256, SM_GEMM_TOTAL>>>(
        xf, wqkv, nullptr, q, kv, 3 * DMODEL);

    // 3) attention on tensor cores
    flash_mma<<<dim3(SEQ / 128, NHEADS, BATCH), 256, SM_FLASH>>>(q, kv, o);

    // 4) output projection (fp32 epilogue)
    gemm_mma<0><<<dim3(DMODEL / 128, ROWS / 128), 256, SM_GEMM_TOTAL>>>(
        o, wo, out, nullptr, nullptr, DMODEL);
}